// round 10
// baseline (speedup 1.0000x reference)
#include <cuda_runtime.h>
#include <math.h>
#include <stdint.h>

#define TOK   65536      // B * NFEATS
#define BSAMP 2048
#define HEADS 8
#define INNER 512
#define DICOL 256
#define DIROW 1024
#define DEPTH 4
#define LN_EPS 1e-5f
#define KTILES (BSAMP / 64)

// round fp32 -> tf32 (tensor-core operand quantization)
__device__ __forceinline__ float tf32(float x) {
    uint32_t u;
    asm("cvt.rna.tf32.f32 %0, %1;" : "=r"(u) : "f"(x));
    return __uint_as_float(u);
}

__device__ __forceinline__ void mma_tf32(float* c, const uint32_t* a, const uint32_t* b) {
    asm volatile(
        "mma.sync.aligned.m16n8k8.row.col.f32.tf32.tf32.f32 "
        "{%0,%1,%2,%3}, {%4,%5,%6,%7}, {%8,%9}, {%0,%1,%2,%3};"
        : "+f"(c[0]), "+f"(c[1]), "+f"(c[2]), "+f"(c[3])
        : "r"(a[0]), "r"(a[1]), "r"(a[2]), "r"(a[3]), "r"(b[0]), "r"(b[1]));
}

__device__ __forceinline__ void cp_async16(uint32_t saddr, const void* gptr) {
    asm volatile("cp.async.cg.shared.global [%0], [%1], 16;" :: "r"(saddr), "l"(gptr));
}
__device__ __forceinline__ void cp_commit() { asm volatile("cp.async.commit_group;"); }
template<int N> __device__ __forceinline__ void cp_wait() {
    asm volatile("cp.async.wait_group %0;" :: "n"(N));
}
__device__ __forceinline__ uint32_t smem_u32(const void* p) {
    return (uint32_t)__cvta_generic_to_shared(p);
}

// ---------------- static scratch ----------------
__device__ float g_x  [TOK * 64];
__device__ float g_xn [TOK * 64];          // exact LN output (residual path)
__device__ float g_xnr[TOK * 64];          // tf32-rounded LN output (GEMM A path)
__device__ float g_qkv[TOK * 3 * INNER];
__device__ float g_at [TOK * INNER];       // attention out (tf32-rounded at write)
__device__ float g_h  [TOK * 2 * DICOL];   // mlp hidden (exact)
__device__ float g_g  [TOK * DICOL];       // geglu out (tf32-rounded at write)
__device__ float g_wr [42663936];          // tf32-rounded weights

// rounded-weight scratch offsets (floats)
#define OFF_CQKV 0
#define OFF_CWO  393216
#define OFF_CW1  524288
#define OFF_CW2  655360
#define OFF_RQKV 720896
#define OFF_RWO  13303808
#define OFF_RW1  17498112
#define OFF_RW2  34275328

__global__ void k_round(const float* __restrict__ in, float* __restrict__ out, int n) {
    int i = blockIdx.x * 256 + threadIdx.x;
    if (i < n) out[i] = tf32(in[i]);
}

// ---------------- concat ----------------
__global__ void k_concat(const float* __restrict__ x, const float* __restrict__ xc,
                         float* __restrict__ out) {
    int i = blockIdx.x * 256 + threadIdx.x;
    if (i >= TOK * 64) return;
    int d = i & 63;
    int t = i >> 6;
    int f = t & 31;
    int s = t >> 5;
    float v = (f < 16) ? x[(s * 16 + f) * 64 + d] : xc[(s * 16 + (f - 16)) * 64 + d];
    out[i] = v;
}

// ---------------- LayerNorm 64: writes exact + rounded ----------------
__global__ void k_ln64(const float* __restrict__ in, const float* __restrict__ g,
                       const float* __restrict__ b, float* __restrict__ out,
                       float* __restrict__ outr) {
    int warp = (blockIdx.x * blockDim.x + threadIdx.x) >> 5;
    int lane = threadIdx.x & 31;
    if (warp >= TOK) return;
    const float* r = in + warp * 64;
    float v0 = r[lane], v1 = r[lane + 32];
    float s = v0 + v1;
    #pragma unroll
    for (int o = 16; o; o >>= 1) s += __shfl_xor_sync(0xffffffffu, s, o);
    float m = s * (1.f / 64.f);
    float d0 = v0 - m, d1 = v1 - m;
    float q = d0 * d0 + d1 * d1;
    #pragma unroll
    for (int o = 16; o; o >>= 1) q += __shfl_xor_sync(0xffffffffu, q, o);
    float inv = rsqrtf(q * (1.f / 64.f) + LN_EPS);
    float y0 = d0 * inv * g[lane]      + b[lane];
    float y1 = d1 * inv * g[lane + 32] + b[lane + 32];
    out [warp * 64 + lane]      = y0;
    out [warp * 64 + lane + 32] = y1;
    outr[warp * 64 + lane]      = tf32(y0);
    outr[warp * 64 + lane + 32] = tf32(y1);
}

// ---------------- LayerNorm 2048: writes exact + rounded ----------------
__global__ void k_ln2048(const float* __restrict__ in, const float* __restrict__ g,
                         const float* __restrict__ b, float* __restrict__ out,
                         float* __restrict__ outr) {
    int row = blockIdx.x;
    const float* r = in + row * 2048;
    float local[8];
    float s = 0.f;
    #pragma unroll
    for (int i = 0; i < 8; i++) { local[i] = r[threadIdx.x + i * 256]; s += local[i]; }
    __shared__ float red[256];
    red[threadIdx.x] = s; __syncthreads();
    for (int o = 128; o; o >>= 1) { if (threadIdx.x < o) red[threadIdx.x] += red[threadIdx.x + o]; __syncthreads(); }
    float m = red[0] * (1.f / 2048.f);
    __syncthreads();
    float q = 0.f;
    #pragma unroll
    for (int i = 0; i < 8; i++) { float d = local[i] - m; q += d * d; }
    red[threadIdx.x] = q; __syncthreads();
    for (int o = 128; o; o >>= 1) { if (threadIdx.x < o) red[threadIdx.x] += red[threadIdx.x + o]; __syncthreads(); }
    float inv = rsqrtf(red[0] * (1.f / 2048.f) + LN_EPS);
    #pragma unroll
    for (int i = 0; i < 8; i++) {
        int c = threadIdx.x + i * 256;
        float y = (local[i] - m) * inv * g[c] + b[c];
        out [row * 2048 + c] = y;
        outr[row * 2048 + c] = tf32(y);
    }
}

// ---------------- pipelined TF32 tensor-core GEMM (operands pre-rounded) ----------------
// C = A[M,K] @ W[K,N] (+bias)(+res). BM=128, BK=16, 3-stage cp.async, dynamic smem.
// BN=256: warps 2x4, WM=64, WN=64. BN=64: warps 4x2, WM=32, WN=32.
template<int BN>
__global__ void __launch_bounds__(256)
k_gemm_mma(const float* __restrict__ A, const float* __restrict__ W,
           const float* __restrict__ bias, const float* __restrict__ res,
           float* __restrict__ C, int M, int N, int K) {
    constexpr int BM = 128, BK = 16, STAGES = 3;
    constexpr int AST = BK + 4;      // 20: fragment loads conflict-free
    constexpr int BST = BN + 8;
    constexpr int WN = (BN == 256) ? 64 : 32;
    constexpr int WARPS_N = BN / WN;             // 4 or 2
    constexpr int WARPS_M = 8 / WARPS_N;         // 2 or 4
    constexpr int WM = BM / WARPS_M;             // 64 or 32
    constexpr int MT = WM / 16;                  // 4 or 2
    constexpr int NT = WN / 8;                   // 8 or 4
    constexpr int A_WORDS = BM * AST;
    extern __shared__ float sm[];
    float* Asm = sm;                             // [STAGES][BM][AST]
    float* Bsm = sm + STAGES * A_WORDS;          // [STAGES][BK][BST]

    int tid  = threadIdx.x;
    int warp = tid >> 5, lane = tid & 31;
    int gid  = lane >> 2, tg = lane & 3;
    int wm   = warp / WARPS_N, wn = warp % WARPS_N;
    int row0 = blockIdx.y * BM, col0 = blockIdx.x * BN;

    float acc[MT][NT][4];
    #pragma unroll
    for (int i = 0; i < MT; i++)
        #pragma unroll
        for (int j = 0; j < NT; j++)
            #pragma unroll
            for (int q = 0; q < 4; q++) acc[i][j][q] = 0.f;

    const int ntiles = K / BK;

    auto load_tile = [&](int t, int buf) {
        int kt = t * BK;
        float* As = Asm + buf * A_WORDS;
        float* Bs = Bsm + buf * (BK * BST);
        #pragma unroll
        for (int i = 0; i < 2; i++) {            // A: 512 16B-chunks
            int ch = tid + i * 256;
            int m = ch >> 2, kc = (ch & 3) * 4;
            cp_async16(smem_u32(As + m * AST + kc),
                       A + (size_t)(row0 + m) * K + kt + kc);
        }
        #pragma unroll
        for (int i = 0; i < (BK * BN) / (4 * 256); i++) {  // B chunks
            int ch = tid + i * 256;
            int k = ch / (BN / 4), nc = (ch % (BN / 4)) * 4;
            cp_async16(smem_u32(Bs + k * BST + nc),
                       W + (size_t)(kt + k) * N + col0 + nc);
        }
    };

    load_tile(0, 0); cp_commit();
    load_tile(1, 1); cp_commit();

    for (int t = 0; t < ntiles; t++) {
        int buf = t % STAGES;
        if (t + 2 < ntiles) { load_tile(t + 2, (t + 2) % STAGES); cp_commit(); cp_wait<2>(); }
        else if (t + 1 < ntiles) { cp_wait<1>(); }
        else { cp_wait<0>(); }
        __syncthreads();

        const float* As = Asm + buf * A_WORDS;
        const float* Bs = Bsm + buf * (BK * BST);
        #pragma unroll
        for (int ks = 0; ks < BK; ks += 8) {
            uint32_t af[MT][4], bf[NT][2];
            #pragma unroll
            for (int mt = 0; mt < MT; mt++) {
                int m0 = wm * WM + mt * 16;
                af[mt][0] = __float_as_uint(As[(m0 + gid    ) * AST + ks + tg    ]);
                af[mt][1] = __float_as_uint(As[(m0 + gid + 8) * AST + ks + tg    ]);
                af[mt][2] = __float_as_uint(As[(m0 + gid    ) * AST + ks + tg + 4]);
                af[mt][3] = __float_as_uint(As[(m0 + gid + 8) * AST + ks + tg + 4]);
            }
            #pragma unroll
            for (int nt = 0; nt < NT; nt++) {
                int n0 = wn * WN + nt * 8 + gid;
                bf[nt][0] = __float_as_uint(Bs[(ks + tg    ) * BST + n0]);
                bf[nt][1] = __float_as_uint(Bs[(ks + tg + 4) * BST + n0]);
            }
            #pragma unroll
            for (int mt = 0; mt < MT; mt++)
                #pragma unroll
                for (int nt = 0; nt < NT; nt++)
                    mma_tf32(acc[mt][nt], af[mt], bf[nt]);
        }
        __syncthreads();
    }

    #pragma unroll
    for (int mt = 0; mt < MT; mt++) {
        #pragma unroll
        for (int nt = 0; nt < NT; nt++) {
            int r0 = row0 + wm * WM + mt * 16 + gid;
            int c  = col0 + wn * WN + nt * 8 + tg * 2;
            float v0 = acc[mt][nt][0], v1 = acc[mt][nt][1];
            float v2 = acc[mt][nt][2], v3 = acc[mt][nt][3];
            if (bias) {
                float b0 = bias[c], b1 = bias[c + 1];
                v0 += b0; v1 += b1; v2 += b0; v3 += b1;
            }
            if (res) {
                v0 += res[(size_t)r0 * N + c];
                v1 += res[(size_t)r0 * N + c + 1];
                v2 += res[(size_t)(r0 + 8) * N + c];
                v3 += res[(size_t)(r0 + 8) * N + c + 1];
            }
            C[(size_t)r0 * N + c]           = v0;
            C[(size_t)r0 * N + c + 1]       = v1;
            C[(size_t)(r0 + 8) * N + c]     = v2;
            C[(size_t)(r0 + 8) * N + c + 1] = v3;
        }
    }
}

// ---------------- col attention ----------------
__global__ void k_colattn(const float* __restrict__ qkv, float* __restrict__ out) {
    int s = blockIdx.x, h = blockIdx.y;
    __shared__ float q[32][64], k[32][65], v[32][64], p[32][32];
    int tid = threadIdx.x;
    #pragma unroll
    for (int i = 0; i < 8; i++) {
        int idx = tid + i * 256;
        int r = idx >> 6, d = idx & 63;
        int base = (s * 32 + r) * 1536 + h * 64 + d;
        q[r][d] = tf32(qkv[base]);
        k[r][d] = tf32(qkv[base + 512]);
        v[r][d] = tf32(qkv[base + 1024]);
    }
    __syncthreads();
    #pragma unroll
    for (int i = 0; i < 4; i++) {
        int idx = tid + i * 256;
        int r = idx >> 5, c = idx & 31;
        float acc = 0.f;
        #pragma unroll
        for (int d = 0; d < 64; d++) acc += q[r][d] * k[c][d];
        p[r][c] = acc * 0.125f;
    }
    __syncthreads();
    int lane = tid & 31, w = tid >> 5;
    #pragma unroll
    for (int rr = 0; rr < 4; rr++) {
        int r = w * 4 + rr;
        float x = p[r][lane];
        float mx = x;
        #pragma unroll
        for (int o = 16; o; o >>= 1) mx = fmaxf(mx, __shfl_xor_sync(0xffffffffu, mx, o));
        float e = expf(x - mx);
        float sm = e;
        #pragma unroll
        for (int o = 16; o; o >>= 1) sm += __shfl_xor_sync(0xffffffffu, sm, o);
        p[r][lane] = tf32(e / sm);
    }
    __syncthreads();
    #pragma unroll
    for (int i = 0; i < 8; i++) {
        int idx = tid + i * 256;
        int r = idx >> 6, d = idx & 63;
        float acc = 0.f;
        #pragma unroll
        for (int j = 0; j < 32; j++) acc += p[r][j] * v[j][d];
        out[(s * 32 + r) * 512 + h * 64 + d] = tf32(acc);  // rounded: feeds GEMM A
    }
}

// ---------------- row attention: two-pass ----------------
__global__ void k_rowattn(const float* __restrict__ qkv, float* __restrict__ out) {
    int qb = blockIdx.x, h = blockIdx.y;
    __shared__ float qs[32][65];
    __shared__ float ks[64][65];
    __shared__ float vs[64][65];
    int tid = threadIdx.x;
    int row = tid >> 3;
    int cg  = tid & 7;
    #pragma unroll
    for (int i = 0; i < 8; i++) {
        int idx = tid + i * 256;
        int r = idx >> 6, d = idx & 63;
        qs[r][d] = tf32(qkv[(qb * 32 + r) * 1536 + h * 64 + d]);
    }
    __syncthreads();

    float m = -1e30f, l = 0.f;
    for (int kt = 0; kt < KTILES; kt++) {
        #pragma unroll
        for (int i = 0; i < 16; i++) {
            int idx = tid + i * 256;
            int r = idx >> 6, d = idx & 63;
            ks[r][d] = tf32(qkv[(kt * 64 + r) * 1536 + 512 + h * 64 + d]);
        }
        __syncthreads();
        float sv[8];
        float mx = m;
        #pragma unroll
        for (int jj = 0; jj < 8; jj++) {
            int j = cg * 8 + jj;
            float acc = 0.f;
            #pragma unroll
            for (int d = 0; d < 64; d++) acc += qs[row][d] * ks[j][d];
            acc *= 0.125f;
            sv[jj] = acc;
            mx = fmaxf(mx, acc);
        }
        #pragma unroll
        for (int o2 = 1; o2 < 8; o2 <<= 1) mx = fmaxf(mx, __shfl_xor_sync(0xffffffffu, mx, o2));
        float f = expf(m - mx);
        m = mx;
        float ps = 0.f;
        #pragma unroll
        for (int jj = 0; jj < 8; jj++) ps += expf(sv[jj] - mx);
        #pragma unroll
        for (int o2 = 1; o2 < 8; o2 <<= 1) ps += __shfl_xor_sync(0xffffffffu, ps, o2);
        l = l * f + ps;
        __syncthreads();
    }

    float o[8] = {0, 0, 0, 0, 0, 0, 0, 0};
    for (int kt = 0; kt < KTILES; kt++) {
        #pragma unroll
        for (int i = 0; i < 16; i++) {
            int idx = tid + i * 256;
            int r = idx >> 6, d = idx & 63;
            int base = (kt * 64 + r) * 1536 + h * 64 + d;
            ks[r][d] = tf32(qkv[base + 512]);
            vs[r][d] = tf32(qkv[base + 1024]);
        }
        __syncthreads();
        float pv[8];
        #pragma unroll
        for (int jj = 0; jj < 8; jj++) {
            int j = cg * 8 + jj;
            float acc = 0.f;
            #pragma unroll
            for (int d = 0; d < 64; d++) acc += qs[row][d] * ks[j][d];
            acc *= 0.125f;
            pv[jj] = tf32(expf(acc - m) / l);
        }
        __syncthreads();
        #pragma unroll
        for (int jj = 0; jj < 8; jj++) ks[row][cg * 8 + jj] = pv[jj];
        __syncthreads();
        #pragma unroll
        for (int j = 0; j < 64; j++) {
            float pj = ks[row][j];
            #pragma unroll
            for (int dd = 0; dd < 8; dd++) o[dd] += pj * vs[j][cg * 8 + dd];
        }
        __syncthreads();
    }
    #pragma unroll
    for (int dd = 0; dd < 8; dd++)
        out[(qb * 32 + row) * 512 + h * 64 + cg * 8 + dd] = tf32(o[dd]);  // feeds GEMM A
}

// ---------------- GEGLU (rounded output: feeds GEMM A) ----------------
__global__ void k_geglu(const float* __restrict__ h, float* __restrict__ out, int M, int F) {
    int i = blockIdx.x * 256 + threadIdx.x;
    if (i >= M * F) return;
    int r = i / F, c = i - r * F;
    float a = h[r * 2 * F + c];
    float g = h[r * 2 * F + F + c];
    out[i] = tf32(a * 0.5f * g * (1.f + erff(g * 0.70710678118654752f)));
}

__global__ void k_copy(const float* __restrict__ in, float* __restrict__ out, int n) {
    int i = blockIdx.x * 256 + threadIdx.x;
    if (i < n) out[i] = in[i];
}

// ---------------- driver ----------------
extern "C" void kernel_launch(void* const* d_in, const int* in_sizes, int n_in,
                              void* d_out, int out_size) {
    const float* x       = (const float*)d_in[0];
    const float* x_cont  = (const float*)d_in[1];
    const float* c_ln1_g = (const float*)d_in[2];
    const float* c_ln1_b = (const float*)d_in[3];
    const float* c_wqkv  = (const float*)d_in[4];
    const float* c_wo_w  = (const float*)d_in[5];
    const float* c_wo_b  = (const float*)d_in[6];
    const float* c_ln2_g = (const float*)d_in[7];
    const float* c_ln2_b = (const float*)d_in[8];
    const float* c_w1    = (const float*)d_in[9];
    const float* c_b1    = (const float*)d_in[10];
    const float* c_w2    = (const float*)d_in[11];
    const float* c_b2    = (const float*)d_in[12];
    const float* r_ln1_g = (const float*)d_in[13];
    const float* r_ln1_b = (const float*)d_in[14];
    const float* r_wqkv  = (const float*)d_in[15];
    const float* r_wo_w  = (const float*)d_in[16];
    const float* r_wo_b  = (const float*)d_in[17];
    const float* r_ln2_g = (const float*)d_in[18];
    const float* r_ln2_b = (const float*)d_in[19];
    const float* r_w1    = (const float*)d_in[20];
    const float* r_b1    = (const float*)d_in[21];
    const float* r_w2    = (const float*)d_in[22];
    const float* r_b2    = (const float*)d_in[23];

    float *px, *pxn, *pxnr, *pqkv, *pat, *ph, *pg, *pwr;
    cudaGetSymbolAddress((void**)&px,   g_x);
    cudaGetSymbolAddress((void**)&pxn,  g_xn);
    cudaGetSymbolAddress((void**)&pxnr, g_xnr);
    cudaGetSymbolAddress((void**)&pqkv, g_qkv);
    cudaGetSymbolAddress((void**)&pat,  g_at);
    cudaGetSymbolAddress((void**)&ph,   g_h);
    cudaGetSymbolAddress((void**)&pg,   g_g);
    cudaGetSymbolAddress((void**)&pwr,  g_wr);

    // dynamic smem sizes for the GEMM variants
    const int SM256 = 3 * (128 * 20 + 16 * 264) * 4;  // 81408 B
    const int SM64  = 3 * (128 * 20 + 16 * 72) * 4;   // 44544 B
    cudaFuncSetAttribute(k_gemm_mma<256>, cudaFuncAttributeMaxDynamicSharedMemorySize, SM256);
    cudaFuncSetAttribute(k_gemm_mma<64>,  cudaFuncAttributeMaxDynamicSharedMemorySize, SM64);

    // pre-round all weights into scratch (tf32 operand quantization)
    k_round<<<(4 * 64 * 1536) / 256, 256>>>(c_wqkv, pwr + OFF_CQKV, 4 * 64 * 1536);
    k_round<<<(4 * 512 * 64) / 256, 256>>>(c_wo_w, pwr + OFF_CWO, 4 * 512 * 64);
    k_round<<<(4 * 64 * 512) / 256, 256>>>(c_w1, pwr + OFF_CW1, 4 * 64 * 512);
    k_round<<<(4 * 256 * 64) / 256, 256>>>(c_w2, pwr + OFF_CW2, 4 * 256 * 64);
    k_round<<<(4 * 2048 * 1536) / 256, 256>>>(r_wqkv, pwr + OFF_RQKV, 4 * 2048 * 1536);
    k_round<<<(4 * 512 * 2048) / 256, 256>>>(r_wo_w, pwr + OFF_RWO, 4 * 512 * 2048);
    k_round<<<(4 * 2048 * 2048) / 256, 256>>>(r_w1, pwr + OFF_RW1, 4 * 2048 * 2048);
    k_round<<<(4 * 1024 * 2048) / 256, 256>>>(r_w2, pwr + OFF_RW2, 4 * 1024 * 2048);

    k_concat<<<(TOK * 64) / 256, 256>>>(x, x_cont, px);

    for (int L = 0; L < DEPTH; L++) {
        // ----- col block -----
        k_ln64<<<TOK / 8, 256>>>(px, c_ln1_g + L * 64, c_ln1_b + L * 64, pxn, pxnr);
        k_gemm_mma<256><<<dim3(6, 512), 256, SM256>>>(
            pxnr, pwr + OFF_CQKV + L * 64 * 1536, nullptr, nullptr, pqkv, TOK, 1536, 64);
        k_colattn<<<dim3(BSAMP, HEADS), 256>>>(pqkv, pat);
        k_gemm_mma<64><<<dim3(1, 512), 256, SM64>>>(
            pat, pwr + OFF_CWO + L * 512 * 64, c_wo_b + L * 64, pxn, px, TOK, 64, 512);
        k_ln64<<<TOK / 8, 256>>>(px, c_ln2_g + L * 64, c_ln2_b + L * 64, pxn, pxnr);
        k_gemm_mma<256><<<dim3(2, 512), 256, SM256>>>(
            pxnr, pwr + OFF_CW1 + L * 64 * 512, c_b1 + L * 512, nullptr, ph, TOK, 512, 64);
        k_geglu<<<(TOK * DICOL) / 256, 256>>>(ph, pg, TOK, DICOL);
        k_gemm_mma<64><<<dim3(1, 512), 256, SM64>>>(
            pg, pwr + OFF_CW2 + L * 256 * 64, c_b2 + L * 64, pxn, px, TOK, 64, 256);

        // ----- row block -----
        k_ln2048<<<BSAMP, 256>>>(px, r_ln1_g + L * 2048, r_ln1_b + L * 2048, pxn, pxnr);
        k_gemm_mma<256><<<dim3(6, 16), 256, SM256>>>(
            pxnr, pwr + OFF_RQKV + (size_t)L * 2048 * 1536, nullptr, nullptr, pqkv, BSAMP, 1536, 2048);
        k_rowattn<<<dim3(BSAMP / 32, HEADS), 256>>>(pqkv, pat);
        k_gemm_mma<256><<<dim3(8, 16), 256, SM256>>>(
            pat, pwr + OFF_RWO + (size_t)L * 512 * 2048, r_wo_b + L * 2048, pxn, px, BSAMP, 2048, 512);
        k_ln2048<<<BSAMP, 256>>>(px, r_ln2_g + L * 2048, r_ln2_b + L * 2048, pxn, pxnr);
        k_gemm_mma<256><<<dim3(8, 16), 256, SM256>>>(
            pxnr, pwr + OFF_RW1 + (size_t)L * 2048 * 2048, r_b1 + L * 2048, nullptr, ph, BSAMP, 2048, 2048);
        k_geglu<<<(BSAMP * DIROW) / 256, 256>>>(ph, pg, BSAMP, DIROW);
        k_gemm_mma<256><<<dim3(8, 16), 256, SM256>>>(
            pg, pwr + OFF_RW2 + (size_t)L * 1024 * 2048, r_b2 + L * 2048, pxn, px, BSAMP, 2048, 1024);
    }

    k_copy<<<(TOK * 64) / 256, 256>>>(px, (float*)d_out, TOK * 64);
}

// round 14
// speedup vs baseline: 1.2237x; 1.2237x over previous
#include <cuda_runtime.h>
#include <math.h>
#include <stdint.h>

#define TOK   65536      // B * NFEATS
#define BSAMP 2048
#define HEADS 8
#define INNER 512
#define DICOL 256
#define DIROW 1024
#define DEPTH 4
#define LN_EPS 1e-5f
#define KTILES (BSAMP / 64)

// round fp32 -> tf32 (tensor-core operand quantization)
__device__ __forceinline__ float tf32(float x) {
    uint32_t u;
    asm("cvt.rna.tf32.f32 %0, %1;" : "=r"(u) : "f"(x));
    return __uint_as_float(u);
}

__device__ __forceinline__ void mma_tf32(float* c, const uint32_t* a, const uint32_t* b) {
    asm volatile(
        "mma.sync.aligned.m16n8k8.row.col.f32.tf32.tf32.f32 "
        "{%0,%1,%2,%3}, {%4,%5,%6,%7}, {%8,%9}, {%0,%1,%2,%3};"
        : "+f"(c[0]), "+f"(c[1]), "+f"(c[2]), "+f"(c[3])
        : "r"(a[0]), "r"(a[1]), "r"(a[2]), "r"(a[3]), "r"(b[0]), "r"(b[1]));
}

__device__ __forceinline__ void cp_async16(uint32_t saddr, const void* gptr) {
    asm volatile("cp.async.cg.shared.global [%0], [%1], 16;" :: "r"(saddr), "l"(gptr));
}
__device__ __forceinline__ void cp_commit() { asm volatile("cp.async.commit_group;"); }
template<int N> __device__ __forceinline__ void cp_wait() {
    asm volatile("cp.async.wait_group %0;" :: "n"(N));
}
__device__ __forceinline__ uint32_t smem_u32(const void* p) {
    return (uint32_t)__cvta_generic_to_shared(p);
}

// ---------------- static scratch ----------------
__device__ float g_x  [TOK * 64];
__device__ float g_xn [TOK * 64];          // exact LN output (residual path)
__device__ float g_xnr[TOK * 64];          // tf32-rounded LN output (GEMM A path)
__device__ float g_qkv[TOK * 3 * INNER];
__device__ float g_at [TOK * INNER];       // attention out (tf32-rounded at write)
__device__ float g_h  [TOK * 2 * DICOL];   // mlp hidden (exact)
__device__ float g_g  [TOK * DICOL];       // geglu out (tf32-rounded at write)
__device__ float g_wr [42663936];          // tf32-rounded weights

#define OFF_CQKV 0
#define OFF_CWO  393216
#define OFF_CW1  524288
#define OFF_CW2  655360
#define OFF_RQKV 720896
#define OFF_RWO  13303808
#define OFF_RW1  17498112
#define OFF_RW2  34275328

__global__ void k_round(const float* __restrict__ in, float* __restrict__ out, int n) {
    int i = blockIdx.x * 256 + threadIdx.x;
    if (i < n) out[i] = tf32(in[i]);
}

// ---------------- concat ----------------
__global__ void k_concat(const float* __restrict__ x, const float* __restrict__ xc,
                         float* __restrict__ out) {
    int i = blockIdx.x * 256 + threadIdx.x;
    if (i >= TOK * 64) return;
    int d = i & 63;
    int t = i >> 6;
    int f = t & 31;
    int s = t >> 5;
    float v = (f < 16) ? x[(s * 16 + f) * 64 + d] : xc[(s * 16 + (f - 16)) * 64 + d];
    out[i] = v;
}

// ---------------- LayerNorm 64: exact + rounded ----------------
__global__ void k_ln64(const float* __restrict__ in, const float* __restrict__ g,
                       const float* __restrict__ b, float* __restrict__ out,
                       float* __restrict__ outr) {
    int warp = (blockIdx.x * blockDim.x + threadIdx.x) >> 5;
    int lane = threadIdx.x & 31;
    if (warp >= TOK) return;
    const float* r = in + warp * 64;
    float v0 = r[lane], v1 = r[lane + 32];
    float s = v0 + v1;
    #pragma unroll
    for (int o = 16; o; o >>= 1) s += __shfl_xor_sync(0xffffffffu, s, o);
    float m = s * (1.f / 64.f);
    float d0 = v0 - m, d1 = v1 - m;
    float q = d0 * d0 + d1 * d1;
    #pragma unroll
    for (int o = 16; o; o >>= 1) q += __shfl_xor_sync(0xffffffffu, q, o);
    float inv = rsqrtf(q * (1.f / 64.f) + LN_EPS);
    float y0 = d0 * inv * g[lane]      + b[lane];
    float y1 = d1 * inv * g[lane + 32] + b[lane + 32];
    out [warp * 64 + lane]      = y0;
    out [warp * 64 + lane + 32] = y1;
    outr[warp * 64 + lane]      = tf32(y0);
    outr[warp * 64 + lane + 32] = tf32(y1);
}

// ---------------- LayerNorm 2048: exact + rounded ----------------
__global__ void k_ln2048(const float* __restrict__ in, const float* __restrict__ g,
                         const float* __restrict__ b, float* __restrict__ out,
                         float* __restrict__ outr) {
    int row = blockIdx.x;
    const float* r = in + row * 2048;
    float local[8];
    float s = 0.f;
    #pragma unroll
    for (int i = 0; i < 8; i++) { local[i] = r[threadIdx.x + i * 256]; s += local[i]; }
    __shared__ float red[256];
    red[threadIdx.x] = s; __syncthreads();
    for (int o = 128; o; o >>= 1) { if (threadIdx.x < o) red[threadIdx.x] += red[threadIdx.x + o]; __syncthreads(); }
    float m = red[0] * (1.f / 2048.f);
    __syncthreads();
    float q = 0.f;
    #pragma unroll
    for (int i = 0; i < 8; i++) { float d = local[i] - m; q += d * d; }
    red[threadIdx.x] = q; __syncthreads();
    for (int o = 128; o; o >>= 1) { if (threadIdx.x < o) red[threadIdx.x] += red[threadIdx.x + o]; __syncthreads(); }
    float inv = rsqrtf(red[0] * (1.f / 2048.f) + LN_EPS);
    #pragma unroll
    for (int i = 0; i < 8; i++) {
        int c = threadIdx.x + i * 256;
        float y = (local[i] - m) * inv * g[c] + b[c];
        out [row * 2048 + c] = y;
        outr[row * 2048 + c] = tf32(y);
    }
}

// ---------------- pipelined TF32 tensor-core GEMM (pre-rounded operands) ----------------
// C = A[M,K] @ W[K,N] (+bias)(+res). BM=128, BK=16, 2-stage cp.async, static smem.
template<int BN>
__global__ void __launch_bounds__(256)
k_gemm_mma(const float* __restrict__ A, const float* __restrict__ W,
           const float* __restrict__ bias, const float* __restrict__ res,
           float* __restrict__ C, int M, int N, int K) {
    constexpr int BM = 128, BK = 16;
    constexpr int AST = BK + 4;                // 20: fragment loads conflict-free
    constexpr int BST = BN + 8;
    constexpr int WN = 32;
    constexpr int WM = (BN == 128) ? 64 : 32;
    constexpr int WARPS_N = BN / WN;
    constexpr int MT = WM / 16;
    constexpr int NT = WN / 8;
    __shared__ float As[2][BM][AST];
    __shared__ float Bs[2][BK][BST];

    int tid  = threadIdx.x;
    int warp = tid >> 5, lane = tid & 31;
    int gid  = lane >> 2, tg = lane & 3;
    int wm   = warp / WARPS_N, wn = warp % WARPS_N;
    int row0 = blockIdx.y * BM, col0 = blockIdx.x * BN;

    float acc[MT][NT][4];
    #pragma unroll
    for (int i = 0; i < MT; i++)
        #pragma unroll
        for (int j = 0; j < NT; j++)
            #pragma unroll
            for (int q = 0; q < 4; q++) acc[i][j][q] = 0.f;

    const int ntiles = K / BK;

    auto load_tile = [&](int t, int buf) {
        int kt = t * BK;
        #pragma unroll
        for (int i = 0; i < 2; i++) {
            int ch = tid + i * 256;
            int m = ch >> 2, kc = (ch & 3) * 4;
            cp_async16(smem_u32(&As[buf][m][kc]),
                       A + (size_t)(row0 + m) * K + kt + kc);
        }
        #pragma unroll
        for (int i = 0; i < (BK * BN) / (4 * 256); i++) {
            int ch = tid + i * 256;
            int k = ch / (BN / 4), nc = (ch % (BN / 4)) * 4;
            cp_async16(smem_u32(&Bs[buf][k][nc]),
                       W + (size_t)(kt + k) * N + col0 + nc);
        }
    };

    load_tile(0, 0);
    cp_commit();

    for (int t = 0; t < ntiles; t++) {
        int buf = t & 1;
        if (t + 1 < ntiles) {
            load_tile(t + 1, buf ^ 1);
            cp_commit();
            cp_wait<1>();
        } else {
            cp_wait<0>();
        }
        __syncthreads();

        #pragma unroll
        for (int ks = 0; ks < BK; ks += 8) {
            uint32_t af[MT][4], bf[NT][2];
            #pragma unroll
            for (int mt = 0; mt < MT; mt++) {
                int m0 = wm * WM + mt * 16;
                af[mt][0] = __float_as_uint(As[buf][m0 + gid    ][ks + tg    ]);
                af[mt][1] = __float_as_uint(As[buf][m0 + gid + 8][ks + tg    ]);
                af[mt][2] = __float_as_uint(As[buf][m0 + gid    ][ks + tg + 4]);
                af[mt][3] = __float_as_uint(As[buf][m0 + gid + 8][ks + tg + 4]);
            }
            #pragma unroll
            for (int nt = 0; nt < NT; nt++) {
                int n0 = wn * WN + nt * 8 + gid;
                bf[nt][0] = __float_as_uint(Bs[buf][ks + tg    ][n0]);
                bf[nt][1] = __float_as_uint(Bs[buf][ks + tg + 4][n0]);
            }
            #pragma unroll
            for (int mt = 0; mt < MT; mt++)
                #pragma unroll
                for (int nt = 0; nt < NT; nt++)
                    mma_tf32(acc[mt][nt], af[mt], bf[nt]);
        }
        __syncthreads();
    }

    #pragma unroll
    for (int mt = 0; mt < MT; mt++) {
        #pragma unroll
        for (int nt = 0; nt < NT; nt++) {
            int r0 = row0 + wm * WM + mt * 16 + gid;
            int c  = col0 + wn * WN + nt * 8 + tg * 2;
            float v0 = acc[mt][nt][0], v1 = acc[mt][nt][1];
            float v2 = acc[mt][nt][2], v3 = acc[mt][nt][3];
            if (bias) {
                float b0 = bias[c], b1 = bias[c + 1];
                v0 += b0; v1 += b1; v2 += b0; v3 += b1;
            }
            if (res) {
                v0 += res[(size_t)r0 * N + c];
                v1 += res[(size_t)r0 * N + c + 1];
                v2 += res[(size_t)(r0 + 8) * N + c];
                v3 += res[(size_t)(r0 + 8) * N + c + 1];
            }
            C[(size_t)r0 * N + c]           = v0;
            C[(size_t)r0 * N + c + 1]       = v1;
            C[(size_t)(r0 + 8) * N + c]     = v2;
            C[(size_t)(r0 + 8) * N + c + 1] = v3;
        }
    }
}

// ---------------- col attention ----------------
__global__ void k_colattn(const float* __restrict__ qkv, float* __restrict__ out) {
    int s = blockIdx.x, h = blockIdx.y;
    __shared__ float q[32][64], k[32][65], v[32][64], p[32][32];
    int tid = threadIdx.x;
    #pragma unroll
    for (int i = 0; i < 8; i++) {
        int idx = tid + i * 256;
        int r = idx >> 6, d = idx & 63;
        int base = (s * 32 + r) * 1536 + h * 64 + d;
        q[r][d] = tf32(qkv[base]);
        k[r][d] = tf32(qkv[base + 512]);
        v[r][d] = tf32(qkv[base + 1024]);
    }
    __syncthreads();
    #pragma unroll
    for (int i = 0; i < 4; i++) {
        int idx = tid + i * 256;
        int r = idx >> 5, c = idx & 31;
        float acc = 0.f;
        #pragma unroll
        for (int d = 0; d < 64; d++) acc += q[r][d] * k[c][d];
        p[r][c] = acc * 0.125f;
    }
    __syncthreads();
    int lane = tid & 31, w = tid >> 5;
    #pragma unroll
    for (int rr = 0; rr < 4; rr++) {
        int r = w * 4 + rr;
        float x = p[r][lane];
        float mx = x;
        #pragma unroll
        for (int o = 16; o; o >>= 1) mx = fmaxf(mx, __shfl_xor_sync(0xffffffffu, mx, o));
        float e = expf(x - mx);
        float sm2 = e;
        #pragma unroll
        for (int o = 16; o; o >>= 1) sm2 += __shfl_xor_sync(0xffffffffu, sm2, o);
        p[r][lane] = tf32(e / sm2);
    }
    __syncthreads();
    #pragma unroll
    for (int i = 0; i < 8; i++) {
        int idx = tid + i * 256;
        int r = idx >> 6, d = idx & 63;
        float acc = 0.f;
        #pragma unroll
        for (int j = 0; j < 32; j++) acc += p[r][j] * v[j][d];
        out[(s * 32 + r) * 512 + h * 64 + d] = tf32(acc);
    }
}

// ---------------- row attention: single-pass flash, CTA per (32-query tile, head) ----------------
__global__ void k_rowattn(const float* __restrict__ qkv, float* __restrict__ out) {
    int qb = blockIdx.x, h = blockIdx.y;
    __shared__ float qs[32][65];
    __shared__ float ks[64][65];   // reused to hold p tile after scores computed
    __shared__ float vs[64][65];
    int tid = threadIdx.x;
    int row = tid >> 3;            // 0..31 query row
    int cg  = tid & 7;             // column group (8 cols each)
    #pragma unroll
    for (int i = 0; i < 8; i++) {
        int idx = tid + i * 256;
        int r = idx >> 6, d = idx & 63;
        qs[r][d] = tf32(qkv[(qb * 32 + r) * 1536 + h * 64 + d]);
    }
    float m = -1e30f, l = 0.f;
    float o[8] = {0, 0, 0, 0, 0, 0, 0, 0};
    __syncthreads();

    for (int kt = 0; kt < KTILES; kt++) {
        #pragma unroll
        for (int i = 0; i < 16; i++) {
            int idx = tid + i * 256;
            int r = idx >> 6, d = idx & 63;
            int base = (kt * 64 + r) * 1536 + h * 64 + d;
            ks[r][d] = tf32(qkv[base + 512]);
            vs[r][d] = tf32(qkv[base + 1024]);
        }
        __syncthreads();
        float sv[8];
        float mx = m;
        #pragma unroll
        for (int jj = 0; jj < 8; jj++) {
            int j = cg * 8 + jj;
            float acc = 0.f;
            #pragma unroll
            for (int d = 0; d < 64; d++) acc += qs[row][d] * ks[j][d];
            acc *= 0.125f;
            sv[jj] = acc;
            mx = fmaxf(mx, acc);
        }
        #pragma unroll
        for (int o2 = 1; o2 < 8; o2 <<= 1) mx = fmaxf(mx, __shfl_xor_sync(0xffffffffu, mx, o2));
        float f = expf(m - mx);
        m = mx;
        float ps = 0.f;
        #pragma unroll
        for (int jj = 0; jj < 8; jj++) { sv[jj] = expf(sv[jj] - mx); ps += sv[jj]; }
        #pragma unroll
        for (int o2 = 1; o2 < 8; o2 <<= 1) ps += __shfl_xor_sync(0xffffffffu, ps, o2);
        l = l * f + ps;
        #pragma unroll
        for (int dd = 0; dd < 8; dd++) o[dd] *= f;
        __syncthreads();               // all score reads of ks finished
        #pragma unroll
        for (int jj = 0; jj < 8; jj++) ks[row][cg * 8 + jj] = sv[jj];  // p tile into ks
        __syncthreads();
        #pragma unroll
        for (int j = 0; j < 64; j++) {
            float pj = ks[row][j];
            #pragma unroll
            for (int dd = 0; dd < 8; dd++) o[dd] += pj * vs[j][cg * 8 + dd];
        }
        __syncthreads();               // before next tile overwrites ks/vs
    }
    float invl = 1.f / l;
    #pragma unroll
    for (int dd = 0; dd < 8; dd++)
        out[(qb * 32 + row) * 512 + h * 64 + cg * 8 + dd] = tf32(o[dd] * invl);
}

// ---------------- GEGLU (rounded output: feeds GEMM A) ----------------
__global__ void k_geglu(const float* __restrict__ h, float* __restrict__ out, int M, int F) {
    int i = blockIdx.x * 256 + threadIdx.x;
    if (i >= M * F) return;
    int r = i / F, c = i - r * F;
    float a = h[r * 2 * F + c];
    float g = h[r * 2 * F + F + c];
    out[i] = tf32(a * 0.5f * g * (1.f + erff(g * 0.70710678118654752f)));
}

__global__ void k_copy(const float* __restrict__ in, float* __restrict__ out, int n) {
    int i = blockIdx.x * 256 + threadIdx.x;
    if (i < n) out[i] = in[i];
}

// ---------------- driver ----------------
extern "C" void kernel_launch(void* const* d_in, const int* in_sizes, int n_in,
                              void* d_out, int out_size) {
    const float* x       = (const float*)d_in[0];
    const float* x_cont  = (const float*)d_in[1];
    const float* c_ln1_g = (const float*)d_in[2];
    const float* c_ln1_b = (const float*)d_in[3];
    const float* c_wqkv  = (const float*)d_in[4];
    const float* c_wo_w  = (const float*)d_in[5];
    const float* c_wo_b  = (const float*)d_in[6];
    const float* c_ln2_g = (const float*)d_in[7];
    const float* c_ln2_b = (const float*)d_in[8];
    const float* c_w1    = (const float*)d_in[9];
    const float* c_b1    = (const float*)d_in[10];
    const float* c_w2    = (const float*)d_in[11];
    const float* c_b2    = (const float*)d_in[12];
    const float* r_ln1_g = (const float*)d_in[13];
    const float* r_ln1_b = (const float*)d_in[14];
    const float* r_wqkv  = (const float*)d_in[15];
    const float* r_wo_w  = (const float*)d_in[16];
    const float* r_wo_b  = (const float*)d_in[17];
    const float* r_ln2_g = (const float*)d_in[18];
    const float* r_ln2_b = (const float*)d_in[19];
    const float* r_w1    = (const float*)d_in[20];
    const float* r_b1    = (const float*)d_in[21];
    const float* r_w2    = (const float*)d_in[22];
    const float* r_b2    = (const float*)d_in[23];

    float *px, *pxn, *pxnr, *pqkv, *pat, *ph, *pg, *pwr;
    cudaGetSymbolAddress((void**)&px,   g_x);
    cudaGetSymbolAddress((void**)&pxn,  g_xn);
    cudaGetSymbolAddress((void**)&pxnr, g_xnr);
    cudaGetSymbolAddress((void**)&pqkv, g_qkv);
    cudaGetSymbolAddress((void**)&pat,  g_at);
    cudaGetSymbolAddress((void**)&ph,   g_h);
    cudaGetSymbolAddress((void**)&pg,   g_g);
    cudaGetSymbolAddress((void**)&pwr,  g_wr);

    // pre-round all weights (tf32 operand quantization)
    k_round<<<(4 * 64 * 1536) / 256, 256>>>(c_wqkv, pwr + OFF_CQKV, 4 * 64 * 1536);
    k_round<<<(4 * 512 * 64) / 256, 256>>>(c_wo_w, pwr + OFF_CWO, 4 * 512 * 64);
    k_round<<<(4 * 64 * 512) / 256, 256>>>(c_w1, pwr + OFF_CW1, 4 * 64 * 512);
    k_round<<<(4 * 256 * 64) / 256, 256>>>(c_w2, pwr + OFF_CW2, 4 * 256 * 64);
    k_round<<<(4 * 2048 * 1536) / 256, 256>>>(r_wqkv, pwr + OFF_RQKV, 4 * 2048 * 1536);
    k_round<<<(4 * 512 * 2048) / 256, 256>>>(r_wo_w, pwr + OFF_RWO, 4 * 512 * 2048);
    k_round<<<(4 * 2048 * 2048) / 256, 256>>>(r_w1, pwr + OFF_RW1, 4 * 2048 * 2048);
    k_round<<<(4 * 1024 * 2048) / 256, 256>>>(r_w2, pwr + OFF_RW2, 4 * 1024 * 2048);

    k_concat<<<(TOK * 64) / 256, 256>>>(x, x_cont, px);

    for (int L = 0; L < DEPTH; L++) {
        // ----- col block -----
        k_ln64<<<TOK / 8, 256>>>(px, c_ln1_g + L * 64, c_ln1_b + L * 64, pxn, pxnr);
        k_gemm_mma<128><<<dim3(1536 / 128, TOK / 128), 256>>>(
            pxnr, pwr + OFF_CQKV + L * 64 * 1536, nullptr, nullptr, pqkv, TOK, 1536, 64);
        k_colattn<<<dim3(BSAMP, HEADS), 256>>>(pqkv, pat);
        k_gemm_mma<64><<<dim3(1, TOK / 128), 256>>>(
            pat, pwr + OFF_CWO + L * 512 * 64, c_wo_b + L * 64, pxn, px, TOK, 64, 512);
        k_ln64<<<TOK / 8, 256>>>(px, c_ln2_g + L * 64, c_ln2_b + L * 64, pxn, pxnr);
        k_gemm_mma<128><<<dim3(512 / 128, TOK / 128), 256>>>(
            pxnr, pwr + OFF_CW1 + L * 64 * 512, c_b1 + L * 512, nullptr, ph, TOK, 512, 64);
        k_geglu<<<(TOK * DICOL) / 256, 256>>>(ph, pg, TOK, DICOL);
        k_gemm_mma<64><<<dim3(1, TOK / 128), 256>>>(
            pg, pwr + OFF_CW2 + L * 256 * 64, c_b2 + L * 64, pxn, px, TOK, 64, 256);

        // ----- row block (x viewed as [2048, 2048]) -----
        k_ln2048<<<BSAMP, 256>>>(px, r_ln1_g + L * 2048, r_ln1_b + L * 2048, pxn, pxnr);
        k_gemm_mma<128><<<dim3(1536 / 128, BSAMP / 128), 256>>>(
            pxnr, pwr + OFF_RQKV + (size_t)L * 2048 * 1536, nullptr, nullptr, pqkv, BSAMP, 1536, 2048);
        k_rowattn<<<dim3(BSAMP / 32, HEADS), 256>>>(pqkv, pat);
        k_gemm_mma<128><<<dim3(2048 / 128, BSAMP / 128), 256>>>(
            pat, pwr + OFF_RWO + (size_t)L * 512 * 2048, r_wo_b + L * 2048, pxn, px, BSAMP, 2048, 512);
        k_ln2048<<<BSAMP, 256>>>(px, r_ln2_g + L * 2048, r_ln2_b + L * 2048, pxn, pxnr);
        k_gemm_mma<128><<<dim3(2048 / 128, BSAMP / 128), 256>>>(
            pxnr, pwr + OFF_RW1 + (size_t)L * 2048 * 2048, r_b1 + L * 2048, nullptr, ph, BSAMP, 2048, 2048);
        k_geglu<<<(BSAMP * DIROW) / 256, 256>>>(ph, pg, BSAMP, DIROW);
        k_gemm_mma<128><<<dim3(2048 / 128, BSAMP / 128), 256>>>(
            pg, pwr + OFF_RW2 + (size_t)L * 1024 * 2048, r_b2 + L * 2048, pxn, px, BSAMP, 2048, 1024);
    }

    k_copy<<<(TOK * 64) / 256, 256>>>(px, (float*)d_out, TOK * 64);
}

// round 16
// speedup vs baseline: 1.4266x; 1.1658x over previous
#include <cuda_runtime.h>
#include <cuda_fp16.h>
#include <math.h>
#include <stdint.h>

#define TOK   65536      // B * NFEATS
#define BSAMP 2048
#define HEADS 8
#define INNER 512
#define DICOL 256
#define DIROW 1024
#define DEPTH 4
#define LN_EPS 1e-5f
#define KTILES (BSAMP / 64)

__device__ __forceinline__ float tf32(float x) {
    uint32_t u;
    asm("cvt.rna.tf32.f32 %0, %1;" : "=r"(u) : "f"(x));
    return __uint_as_float(u);
}

// m16n8k16 fp16 mma, fp32 accumulate (A row-major, B col-major)
__device__ __forceinline__ void mma_f16(float* c, const uint32_t* a, const uint32_t* b) {
    asm volatile(
        "mma.sync.aligned.m16n8k16.row.col.f32.f16.f16.f32 "
        "{%0,%1,%2,%3}, {%4,%5,%6,%7}, {%8,%9}, {%0,%1,%2,%3};"
        : "+f"(c[0]), "+f"(c[1]), "+f"(c[2]), "+f"(c[3])
        : "r"(a[0]), "r"(a[1]), "r"(a[2]), "r"(a[3]), "r"(b[0]), "r"(b[1]));
}

__device__ __forceinline__ void cp_async16(uint32_t saddr, const void* gptr) {
    asm volatile("cp.async.cg.shared.global [%0], [%1], 16;" :: "r"(saddr), "l"(gptr));
}
__device__ __forceinline__ void cp_commit() { asm volatile("cp.async.commit_group;"); }
template<int N> __device__ __forceinline__ void cp_wait() {
    asm volatile("cp.async.wait_group %0;" :: "n"(N));
}
__device__ __forceinline__ uint32_t smem_u32(const void* p) {
    return (uint32_t)__cvta_generic_to_shared(p);
}

// ---------------- static scratch ----------------
__device__ float   g_x   [TOK * 64];
__device__ float   g_xn  [TOK * 64];        // exact LN output (residual path)
__device__ __half  g_xnrh[TOK * 64];        // fp16 LN output (GEMM A path)
__device__ float   g_qkv [TOK * 3 * INNER];
__device__ __half  g_ath [TOK * INNER];     // attention out (fp16, GEMM A)
__device__ float   g_h   [TOK * 2 * DICOL]; // mlp hidden (exact)
__device__ __half  g_gh  [TOK * DICOL];     // geglu out (fp16, GEMM A)
__device__ uint32_t g_wrh[21331968];        // fp16 weights, k-paired half2

// u32 offsets into g_wrh
#define OFF2_CQKV 0
#define OFF2_CWO  196608
#define OFF2_CW1  262144
#define OFF2_CW2  327680
#define OFF2_RQKV 360448
#define OFF2_RWO  6651904
#define OFF2_RW1  8749056
#define OFF2_RW2  17137664

// pack W[Ktot,N] fp32 -> Wp[Ktot/2,N] u32 of half2 {W[2k2][n], W[2k2+1][n]}
__global__ void k_packh(const float* __restrict__ in, uint32_t* __restrict__ out,
                        int n_out, int N) {
    int i = blockIdx.x * 256 + threadIdx.x;
    if (i >= n_out) return;
    int k2 = i / N, n = i - k2 * N;
    __half lo = __float2half_rn(in[(size_t)(2 * k2) * N + n]);
    __half hi = __float2half_rn(in[(size_t)(2 * k2 + 1) * N + n]);
    out[i] = ((uint32_t)__half_as_ushort(hi) << 16) | __half_as_ushort(lo);
}

// ---------------- concat ----------------
__global__ void k_concat(const float* __restrict__ x, const float* __restrict__ xc,
                         float* __restrict__ out) {
    int i = blockIdx.x * 256 + threadIdx.x;
    if (i >= TOK * 64) return;
    int d = i & 63;
    int t = i >> 6;
    int f = t & 31;
    int s = t >> 5;
    float v = (f < 16) ? x[(s * 16 + f) * 64 + d] : xc[(s * 16 + (f - 16)) * 64 + d];
    out[i] = v;
}

// ---------------- LayerNorm 64: exact + fp16 ----------------
__global__ void k_ln64(const float* __restrict__ in, const float* __restrict__ g,
                       const float* __restrict__ b, float* __restrict__ out,
                       __half* __restrict__ outr) {
    int warp = (blockIdx.x * blockDim.x + threadIdx.x) >> 5;
    int lane = threadIdx.x & 31;
    if (warp >= TOK) return;
    const float* r = in + warp * 64;
    float v0 = r[lane], v1 = r[lane + 32];
    float s = v0 + v1;
    #pragma unroll
    for (int o = 16; o; o >>= 1) s += __shfl_xor_sync(0xffffffffu, s, o);
    float m = s * (1.f / 64.f);
    float d0 = v0 - m, d1 = v1 - m;
    float q = d0 * d0 + d1 * d1;
    #pragma unroll
    for (int o = 16; o; o >>= 1) q += __shfl_xor_sync(0xffffffffu, q, o);
    float inv = rsqrtf(q * (1.f / 64.f) + LN_EPS);
    float y0 = d0 * inv * g[lane]      + b[lane];
    float y1 = d1 * inv * g[lane + 32] + b[lane + 32];
    out [warp * 64 + lane]      = y0;
    out [warp * 64 + lane + 32] = y1;
    outr[warp * 64 + lane]      = __float2half_rn(y0);
    outr[warp * 64 + lane + 32] = __float2half_rn(y1);
}

// ---------------- LayerNorm 2048: exact + fp16 ----------------
__global__ void k_ln2048(const float* __restrict__ in, const float* __restrict__ g,
                         const float* __restrict__ b, float* __restrict__ out,
                         __half* __restrict__ outr) {
    int row = blockIdx.x;
    const float* r = in + row * 2048;
    float local[8];
    float s = 0.f;
    #pragma unroll
    for (int i = 0; i < 8; i++) { local[i] = r[threadIdx.x + i * 256]; s += local[i]; }
    __shared__ float red[256];
    red[threadIdx.x] = s; __syncthreads();
    for (int o = 128; o; o >>= 1) { if (threadIdx.x < o) red[threadIdx.x] += red[threadIdx.x + o]; __syncthreads(); }
    float m = red[0] * (1.f / 2048.f);
    __syncthreads();
    float q = 0.f;
    #pragma unroll
    for (int i = 0; i < 8; i++) { float d = local[i] - m; q += d * d; }
    red[threadIdx.x] = q; __syncthreads();
    for (int o = 128; o; o >>= 1) { if (threadIdx.x < o) red[threadIdx.x] += red[threadIdx.x + o]; __syncthreads(); }
    float inv = rsqrtf(red[0] * (1.f / 2048.f) + LN_EPS);
    #pragma unroll
    for (int i = 0; i < 8; i++) {
        int c = threadIdx.x + i * 256;
        float y = (local[i] - m) * inv * g[c] + b[c];
        out [row * 2048 + c] = y;
        outr[row * 2048 + c] = __float2half_rn(y);
    }
}

// ---------------- pipelined FP16 tensor-core GEMM ----------------
// C = A[M,K](fp16) @ Wp[K/2,N](half2) (+bias)(+res). BM=128, BK=32 halves,
// 2-stage cp.async. BN=128: warps 2x4 (WM=64,WN=32). BN=64: warps 4x2 (WM=32,WN=32).
template<int BN>
__global__ void __launch_bounds__(256)
k_gemm_h(const __half* __restrict__ A, const uint32_t* __restrict__ Wp,
         const float* __restrict__ bias, const float* __restrict__ res,
         float* __restrict__ C, int M, int N, int K) {
    constexpr int BM = 128;
    constexpr int AST2 = 20;                 // u32 per A row (40 halves): bank-clean
    constexpr int BST2 = BN + 8;             // u32 per B row: bank-clean
    constexpr int WN = 32;
    constexpr int WM = (BN == 128) ? 64 : 32;
    constexpr int WARPS_N = BN / WN;
    constexpr int MT = WM / 16;
    constexpr int NT = WN / 8;
    __shared__ uint32_t As[2][BM * AST2];
    __shared__ uint32_t Bs[2][16 * BST2];

    int tid  = threadIdx.x;
    int warp = tid >> 5, lane = tid & 31;
    int gid  = lane >> 2, tg = lane & 3;
    int wm   = warp / WARPS_N, wn = warp % WARPS_N;
    int row0 = blockIdx.y * BM, col0 = blockIdx.x * BN;

    float acc[MT][NT][4];
    #pragma unroll
    for (int i = 0; i < MT; i++)
        #pragma unroll
        for (int j = 0; j < NT; j++)
            #pragma unroll
            for (int q = 0; q < 4; q++) acc[i][j][q] = 0.f;

    const int ntiles = K / 32;

    auto load_tile = [&](int t, int buf) {
        int kt = t * 32;          // halves
        int kt2 = t * 16;         // half2 rows
        #pragma unroll
        for (int i = 0; i < 2; i++) {       // A: 128 rows x 4 chunks of 8 halves
            int ch = tid + i * 256;
            int m = ch >> 2, kc = ch & 3;
            cp_async16(smem_u32(&As[buf][m * AST2 + kc * 4]),
                       A + (size_t)(row0 + m) * K + kt + kc * 8);
        }
        #pragma unroll
        for (int i = 0; i < BN / 64; i++) { // B: 16 rows x BN/4 chunks of 4 u32
            int ch = tid + i * 256;
            int k2 = ch / (BN / 4), nc = ch % (BN / 4);
            cp_async16(smem_u32(&Bs[buf][k2 * BST2 + nc * 4]),
                       Wp + (size_t)(kt2 + k2) * N + col0 + nc * 4);
        }
    };

    load_tile(0, 0);
    cp_commit();

    for (int t = 0; t < ntiles; t++) {
        int buf = t & 1;
        if (t + 1 < ntiles) {
            load_tile(t + 1, buf ^ 1);
            cp_commit();
            cp_wait<1>();
        } else {
            cp_wait<0>();
        }
        __syncthreads();

        #pragma unroll
        for (int ks = 0; ks < 2; ks++) {     // 2 mma K-steps of 16 halves
            uint32_t af[MT][4], bf[NT][2];
            #pragma unroll
            for (int mt = 0; mt < MT; mt++) {
                int m0 = wm * WM + mt * 16;
                af[mt][0] = As[buf][(m0 + gid    ) * AST2 + ks * 8 + tg    ];
                af[mt][1] = As[buf][(m0 + gid + 8) * AST2 + ks * 8 + tg    ];
                af[mt][2] = As[buf][(m0 + gid    ) * AST2 + ks * 8 + tg + 4];
                af[mt][3] = As[buf][(m0 + gid + 8) * AST2 + ks * 8 + tg + 4];
            }
            #pragma unroll
            for (int nt = 0; nt < NT; nt++) {
                int n0 = wn * WN + nt * 8 + gid;
                bf[nt][0] = Bs[buf][(ks * 8 + tg    ) * BST2 + n0];
                bf[nt][1] = Bs[buf][(ks * 8 + tg + 4) * BST2 + n0];
            }
            #pragma unroll
            for (int mt = 0; mt < MT; mt++)
                #pragma unroll
                for (int nt = 0; nt < NT; nt++)
                    mma_f16(acc[mt][nt], af[mt], bf[nt]);
        }
        __syncthreads();
    }

    #pragma unroll
    for (int mt = 0; mt < MT; mt++) {
        #pragma unroll
        for (int nt = 0; nt < NT; nt++) {
            int r0 = row0 + wm * WM + mt * 16 + gid;
            int c  = col0 + wn * WN + nt * 8 + tg * 2;
            float v0 = acc[mt][nt][0], v1 = acc[mt][nt][1];
            float v2 = acc[mt][nt][2], v3 = acc[mt][nt][3];
            if (bias) {
                float b0 = bias[c], b1 = bias[c + 1];
                v0 += b0; v1 += b1; v2 += b0; v3 += b1;
            }
            if (res) {
                v0 += res[(size_t)r0 * N + c];
                v1 += res[(size_t)r0 * N + c + 1];
                v2 += res[(size_t)(r0 + 8) * N + c];
                v3 += res[(size_t)(r0 + 8) * N + c + 1];
            }
            C[(size_t)r0 * N + c]           = v0;
            C[(size_t)r0 * N + c + 1]       = v1;
            C[(size_t)(r0 + 8) * N + c]     = v2;
            C[(size_t)(r0 + 8) * N + c + 1] = v3;
        }
    }
}

// ---------------- col attention ----------------
__global__ void k_colattn(const float* __restrict__ qkv, __half* __restrict__ out) {
    int s = blockIdx.x, h = blockIdx.y;
    __shared__ float q[32][64], k[32][65], v[32][64], p[32][32];
    int tid = threadIdx.x;
    #pragma unroll
    for (int i = 0; i < 8; i++) {
        int idx = tid + i * 256;
        int r = idx >> 6, d = idx & 63;
        int base = (s * 32 + r) * 1536 + h * 64 + d;
        q[r][d] = tf32(qkv[base]);
        k[r][d] = tf32(qkv[base + 512]);
        v[r][d] = tf32(qkv[base + 1024]);
    }
    __syncthreads();
    #pragma unroll
    for (int i = 0; i < 4; i++) {
        int idx = tid + i * 256;
        int r = idx >> 5, c = idx & 31;
        float acc = 0.f;
        #pragma unroll
        for (int d = 0; d < 64; d++) acc += q[r][d] * k[c][d];
        p[r][c] = acc * 0.125f;
    }
    __syncthreads();
    int lane = tid & 31, w = tid >> 5;
    #pragma unroll
    for (int rr = 0; rr < 4; rr++) {
        int r = w * 4 + rr;
        float x = p[r][lane];
        float mx = x;
        #pragma unroll
        for (int o = 16; o; o >>= 1) mx = fmaxf(mx, __shfl_xor_sync(0xffffffffu, mx, o));
        float e = expf(x - mx);
        float sm2 = e;
        #pragma unroll
        for (int o = 16; o; o >>= 1) sm2 += __shfl_xor_sync(0xffffffffu, sm2, o);
        p[r][lane] = tf32(e / sm2);
    }
    __syncthreads();
    #pragma unroll
    for (int i = 0; i < 8; i++) {
        int idx = tid + i * 256;
        int r = idx >> 6, d = idx & 63;
        float acc = 0.f;
        #pragma unroll
        for (int j = 0; j < 32; j++) acc += p[r][j] * v[j][d];
        out[(s * 32 + r) * 512 + h * 64 + d] = __float2half_rn(acc);
    }
}

// ---------------- row attention: single-pass flash ----------------
__global__ void k_rowattn(const float* __restrict__ qkv, __half* __restrict__ out) {
    int qb = blockIdx.x, h = blockIdx.y;
    __shared__ float qs[32][65];
    __shared__ float ks[64][65];
    __shared__ float vs[64][65];
    int tid = threadIdx.x;
    int row = tid >> 3;
    int cg  = tid & 7;
    #pragma unroll
    for (int i = 0; i < 8; i++) {
        int idx = tid + i * 256;
        int r = idx >> 6, d = idx & 63;
        qs[r][d] = tf32(qkv[(qb * 32 + r) * 1536 + h * 64 + d]);
    }
    float m = -1e30f, l = 0.f;
    float o[8] = {0, 0, 0, 0, 0, 0, 0, 0};
    __syncthreads();

    for (int kt = 0; kt < KTILES; kt++) {
        #pragma unroll
        for (int i = 0; i < 16; i++) {
            int idx = tid + i * 256;
            int r = idx >> 6, d = idx & 63;
            int base = (kt * 64 + r) * 1536 + h * 64 + d;
            ks[r][d] = tf32(qkv[base + 512]);
            vs[r][d] = tf32(qkv[base + 1024]);
        }
        __syncthreads();
        float sv[8];
        float mx = m;
        #pragma unroll
        for (int jj = 0; jj < 8; jj++) {
            int j = cg * 8 + jj;
            float acc = 0.f;
            #pragma unroll
            for (int d = 0; d < 64; d++) acc += qs[row][d] * ks[j][d];
            acc *= 0.125f;
            sv[jj] = acc;
            mx = fmaxf(mx, acc);
        }
        #pragma unroll
        for (int o2 = 1; o2 < 8; o2 <<= 1) mx = fmaxf(mx, __shfl_xor_sync(0xffffffffu, mx, o2));
        float f = expf(m - mx);
        m = mx;
        float ps = 0.f;
        #pragma unroll
        for (int jj = 0; jj < 8; jj++) { sv[jj] = expf(sv[jj] - mx); ps += sv[jj]; }
        #pragma unroll
        for (int o2 = 1; o2 < 8; o2 <<= 1) ps += __shfl_xor_sync(0xffffffffu, ps, o2);
        l = l * f + ps;
        #pragma unroll
        for (int dd = 0; dd < 8; dd++) o[dd] *= f;
        __syncthreads();
        #pragma unroll
        for (int jj = 0; jj < 8; jj++) ks[row][cg * 8 + jj] = sv[jj];
        __syncthreads();
        #pragma unroll
        for (int j = 0; j < 64; j++) {
            float pj = ks[row][j];
            #pragma unroll
            for (int dd = 0; dd < 8; dd++) o[dd] += pj * vs[j][cg * 8 + dd];
        }
        __syncthreads();
    }
    float invl = 1.f / l;
    #pragma unroll
    for (int dd = 0; dd < 8; dd++)
        out[(qb * 32 + row) * 512 + h * 64 + cg * 8 + dd] = __float2half_rn(o[dd] * invl);
}

// ---------------- GEGLU ----------------
__global__ void k_geglu(const float* __restrict__ h, __half* __restrict__ out, int M, int F) {
    int i = blockIdx.x * 256 + threadIdx.x;
    if (i >= M * F) return;
    int r = i / F, c = i - r * F;
    float a = h[r * 2 * F + c];
    float g = h[r * 2 * F + F + c];
    out[i] = __float2half_rn(a * 0.5f * g * (1.f + erff(g * 0.70710678118654752f)));
}

__global__ void k_copy(const float* __restrict__ in, float* __restrict__ out, int n) {
    int i = blockIdx.x * 256 + threadIdx.x;
    if (i < n) out[i] = in[i];
}

// ---------------- driver ----------------
extern "C" void kernel_launch(void* const* d_in, const int* in_sizes, int n_in,
                              void* d_out, int out_size) {
    const float* x       = (const float*)d_in[0];
    const float* x_cont  = (const float*)d_in[1];
    const float* c_ln1_g = (const float*)d_in[2];
    const float* c_ln1_b = (const float*)d_in[3];
    const float* c_wqkv  = (const float*)d_in[4];
    const float* c_wo_w  = (const float*)d_in[5];
    const float* c_wo_b  = (const float*)d_in[6];
    const float* c_ln2_g = (const float*)d_in[7];
    const float* c_ln2_b = (const float*)d_in[8];
    const float* c_w1    = (const float*)d_in[9];
    const float* c_b1    = (const float*)d_in[10];
    const float* c_w2    = (const float*)d_in[11];
    const float* c_b2    = (const float*)d_in[12];
    const float* r_ln1_g = (const float*)d_in[13];
    const float* r_ln1_b = (const float*)d_in[14];
    const float* r_wqkv  = (const float*)d_in[15];
    const float* r_wo_w  = (const float*)d_in[16];
    const float* r_wo_b  = (const float*)d_in[17];
    const float* r_ln2_g = (const float*)d_in[18];
    const float* r_ln2_b = (const float*)d_in[19];
    const float* r_w1    = (const float*)d_in[20];
    const float* r_b1    = (const float*)d_in[21];
    const float* r_w2    = (const float*)d_in[22];
    const float* r_b2    = (const float*)d_in[23];

    float *px, *pxn, *pqkv, *ph;
    __half *pxnrh, *path, *pgh;
    uint32_t *pwrh;
    cudaGetSymbolAddress((void**)&px,    g_x);
    cudaGetSymbolAddress((void**)&pxn,   g_xn);
    cudaGetSymbolAddress((void**)&pxnrh, g_xnrh);
    cudaGetSymbolAddress((void**)&pqkv,  g_qkv);
    cudaGetSymbolAddress((void**)&path,  g_ath);
    cudaGetSymbolAddress((void**)&ph,    g_h);
    cudaGetSymbolAddress((void**)&pgh,   g_gh);
    cudaGetSymbolAddress((void**)&pwrh,  g_wrh);

    // pack all weights to k-paired fp16 (n_out = floats/2)
    k_packh<<<(196608) / 256, 256>>>(c_wqkv, pwrh + OFF2_CQKV, 196608, 1536);
    k_packh<<<(65536) / 256, 256>>>(c_wo_w, pwrh + OFF2_CWO, 65536, 64);
    k_packh<<<(65536) / 256, 256>>>(c_w1, pwrh + OFF2_CW1, 65536, 512);
    k_packh<<<(32768) / 256, 256>>>(c_w2, pwrh + OFF2_CW2, 32768, 64);
    k_packh<<<(6291456) / 256, 256>>>(r_wqkv, pwrh + OFF2_RQKV, 6291456, 1536);
    k_packh<<<(2097152) / 256, 256>>>(r_wo_w, pwrh + OFF2_RWO, 2097152, 2048);
    k_packh<<<(8388608) / 256, 256>>>(r_w1, pwrh + OFF2_RW1, 8388608, 2048);
    k_packh<<<(4194304) / 256, 256>>>(r_w2, pwrh + OFF2_RW2, 4194304, 2048);

    k_concat<<<(TOK * 64) / 256, 256>>>(x, x_cont, px);

    for (int L = 0; L < DEPTH; L++) {
        // ----- col block -----
        k_ln64<<<TOK / 8, 256>>>(px, c_ln1_g + L * 64, c_ln1_b + L * 64, pxn, pxnrh);
        k_gemm_h<128><<<dim3(12, 512), 256>>>(
            pxnrh, pwrh + OFF2_CQKV + L * 49152, nullptr, nullptr, pqkv, TOK, 1536, 64);
        k_colattn<<<dim3(BSAMP, HEADS), 256>>>(pqkv, path);
        k_gemm_h<64><<<dim3(1, 512), 256>>>(
            path, pwrh + OFF2_CWO + L * 16384, c_wo_b + L * 64, pxn, px, TOK, 64, 512);
        k_ln64<<<TOK / 8, 256>>>(px, c_ln2_g + L * 64, c_ln2_b + L * 64, pxn, pxnrh);
        k_gemm_h<128><<<dim3(4, 512), 256>>>(
            pxnrh, pwrh + OFF2_CW1 + L * 16384, c_b1 + L * 512, nullptr, ph, TOK, 512, 64);
        k_geglu<<<(TOK * DICOL) / 256, 256>>>(ph, pgh, TOK, DICOL);
        k_gemm_h<64><<<dim3(1, 512), 256>>>(
            pgh, pwrh + OFF2_CW2 + L * 8192, c_b2 + L * 64, pxn, px, TOK, 64, 256);

        // ----- row block (x viewed as [2048, 2048]) -----
        k_ln2048<<<BSAMP, 256>>>(px, r_ln1_g + L * 2048, r_ln1_b + L * 2048, pxn, pxnrh);
        k_gemm_h<128><<<dim3(12, 16), 256>>>(
            pxnrh, pwrh + OFF2_RQKV + (size_t)L * 1572864, nullptr, nullptr, pqkv, BSAMP, 1536, 2048);
        k_rowattn<<<dim3(BSAMP / 32, HEADS), 256>>>(pqkv, path);
        k_gemm_h<128><<<dim3(16, 16), 256>>>(
            path, pwrh + OFF2_RWO + (size_t)L * 524288, r_wo_b + L * 2048, pxn, px, BSAMP, 2048, 512);
        k_ln2048<<<BSAMP, 256>>>(px, r_ln2_g + L * 2048, r_ln2_b + L * 2048, pxn, pxnrh);
        k_gemm_h<128><<<dim3(16, 16), 256>>>(
            pxnrh, pwrh + OFF2_RW1 + (size_t)L * 2097152, r_b1 + L * 2048, nullptr, ph, BSAMP, 2048, 2048);
        k_geglu<<<(BSAMP * DIROW) / 256, 256>>>(ph, pgh, BSAMP, DIROW);
        k_gemm_h<128><<<dim3(16, 16), 256>>>(
            pgh, pwrh + OFF2_RW2 + (size_t)L * 1048576, r_b2 + L * 2048, pxn, px, BSAMP, 2048, 1024);
    }

    k_copy<<<(TOK * 64) / 256, 256>>>(px, (float*)d_out, TOK * 64);
}

// round 17
// speedup vs baseline: 3.2381x; 2.2699x over previous
#include <cuda_runtime.h>
#include <cuda_fp16.h>
#include <math.h>
#include <stdint.h>

#define TOK   65536      // B * NFEATS
#define BSAMP 2048
#define HEADS 8
#define INNER 512
#define DICOL 256
#define DIROW 1024
#define DEPTH 4
#define LN_EPS 1e-5f
#define KTILES (BSAMP / 64)

__device__ __forceinline__ float tf32(float x) {
    uint32_t u;
    asm("cvt.rna.tf32.f32 %0, %1;" : "=r"(u) : "f"(x));
    return __uint_as_float(u);
}
__device__ __forceinline__ uint32_t packh2(float a, float b) {
    __half2 h = __floats2half2_rn(a, b);
    return *(uint32_t*)&h;
}

// m16n8k16 fp16 mma, fp32 accumulate (A row-major, B col-major)
__device__ __forceinline__ void mma_f16(float* c, const uint32_t* a, const uint32_t* b) {
    asm volatile(
        "mma.sync.aligned.m16n8k16.row.col.f32.f16.f16.f32 "
        "{%0,%1,%2,%3}, {%4,%5,%6,%7}, {%8,%9}, {%0,%1,%2,%3};"
        : "+f"(c[0]), "+f"(c[1]), "+f"(c[2]), "+f"(c[3])
        : "r"(a[0]), "r"(a[1]), "r"(a[2]), "r"(a[3]), "r"(b[0]), "r"(b[1]));
}

__device__ __forceinline__ void cp_async16(uint32_t saddr, const void* gptr) {
    asm volatile("cp.async.cg.shared.global [%0], [%1], 16;" :: "r"(saddr), "l"(gptr));
}
__device__ __forceinline__ void cp_commit() { asm volatile("cp.async.commit_group;"); }
template<int N> __device__ __forceinline__ void cp_wait() {
    asm volatile("cp.async.wait_group %0;" :: "n"(N));
}
__device__ __forceinline__ uint32_t smem_u32(const void* p) {
    return (uint32_t)__cvta_generic_to_shared(p);
}

// ---------------- static scratch ----------------
__device__ float    g_x   [TOK * 64];
__device__ float    g_xn  [TOK * 64];        // exact LN output (residual path)
__device__ __half   g_xnrh[TOK * 64];        // fp16 LN output (GEMM A path)
__device__ __half   g_qkvh[TOK * 3 * INNER]; // QKV in fp16
__device__ __half   g_ath [TOK * INNER];     // attention out (fp16, GEMM A)
__device__ float    g_h   [TOK * 2 * DICOL]; // mlp hidden (exact)
__device__ __half   g_gh  [TOK * DICOL];     // geglu out (fp16, GEMM A)
__device__ uint32_t g_wrh [21331968];        // fp16 weights, k-paired half2

// u32 offsets into g_wrh
#define OFF2_CQKV 0
#define OFF2_CWO  196608
#define OFF2_CW1  262144
#define OFF2_CW2  327680
#define OFF2_RQKV 360448
#define OFF2_RWO  6651904
#define OFF2_RW1  8749056
#define OFF2_RW2  17137664

// pack W[Ktot,N] fp32 -> Wp[Ktot/2,N] u32 of half2 {W[2k2][n], W[2k2+1][n]}
__global__ void k_packh(const float* __restrict__ in, uint32_t* __restrict__ out,
                        int n_out, int N) {
    int i = blockIdx.x * 256 + threadIdx.x;
    if (i >= n_out) return;
    int k2 = i / N, n = i - k2 * N;
    __half lo = __float2half_rn(in[(size_t)(2 * k2) * N + n]);
    __half hi = __float2half_rn(in[(size_t)(2 * k2 + 1) * N + n]);
    out[i] = ((uint32_t)__half_as_ushort(hi) << 16) | __half_as_ushort(lo);
}

// ---------------- concat ----------------
__global__ void k_concat(const float* __restrict__ x, const float* __restrict__ xc,
                         float* __restrict__ out) {
    int i = blockIdx.x * 256 + threadIdx.x;
    if (i >= TOK * 64) return;
    int d = i & 63;
    int t = i >> 6;
    int f = t & 31;
    int s = t >> 5;
    float v = (f < 16) ? x[(s * 16 + f) * 64 + d] : xc[(s * 16 + (f - 16)) * 64 + d];
    out[i] = v;
}

// ---------------- LayerNorm 64: exact + fp16 ----------------
__global__ void k_ln64(const float* __restrict__ in, const float* __restrict__ g,
                       const float* __restrict__ b, float* __restrict__ out,
                       __half* __restrict__ outr) {
    int warp = (blockIdx.x * blockDim.x + threadIdx.x) >> 5;
    int lane = threadIdx.x & 31;
    if (warp >= TOK) return;
    const float* r = in + warp * 64;
    float v0 = r[lane], v1 = r[lane + 32];
    float s = v0 + v1;
    #pragma unroll
    for (int o = 16; o; o >>= 1) s += __shfl_xor_sync(0xffffffffu, s, o);
    float m = s * (1.f / 64.f);
    float d0 = v0 - m, d1 = v1 - m;
    float q = d0 * d0 + d1 * d1;
    #pragma unroll
    for (int o = 16; o; o >>= 1) q += __shfl_xor_sync(0xffffffffu, q, o);
    float inv = rsqrtf(q * (1.f / 64.f) + LN_EPS);
    float y0 = d0 * inv * g[lane]      + b[lane];
    float y1 = d1 * inv * g[lane + 32] + b[lane + 32];
    out [warp * 64 + lane]      = y0;
    out [warp * 64 + lane + 32] = y1;
    outr[warp * 64 + lane]      = __float2half_rn(y0);
    outr[warp * 64 + lane + 32] = __float2half_rn(y1);
}

// ---------------- LayerNorm 2048: exact + fp16 ----------------
__global__ void k_ln2048(const float* __restrict__ in, const float* __restrict__ g,
                         const float* __restrict__ b, float* __restrict__ out,
                         __half* __restrict__ outr) {
    int row = blockIdx.x;
    const float* r = in + row * 2048;
    float local[8];
    float s = 0.f;
    #pragma unroll
    for (int i = 0; i < 8; i++) { local[i] = r[threadIdx.x + i * 256]; s += local[i]; }
    __shared__ float red[256];
    red[threadIdx.x] = s; __syncthreads();
    for (int o = 128; o; o >>= 1) { if (threadIdx.x < o) red[threadIdx.x] += red[threadIdx.x + o]; __syncthreads(); }
    float m = red[0] * (1.f / 2048.f);
    __syncthreads();
    float q = 0.f;
    #pragma unroll
    for (int i = 0; i < 8; i++) { float d = local[i] - m; q += d * d; }
    red[threadIdx.x] = q; __syncthreads();
    for (int o = 128; o; o >>= 1) { if (threadIdx.x < o) red[threadIdx.x] += red[threadIdx.x + o]; __syncthreads(); }
    float inv = rsqrtf(red[0] * (1.f / 2048.f) + LN_EPS);
    #pragma unroll
    for (int i = 0; i < 8; i++) {
        int c = threadIdx.x + i * 256;
        float y = (local[i] - m) * inv * g[c] + b[c];
        out [row * 2048 + c] = y;
        outr[row * 2048 + c] = __float2half_rn(y);
    }
}

// ---------------- pipelined FP16 tensor-core GEMM ----------------
// C = A[M,K](fp16) @ Wp[K/2,N](half2) (+bias)(+res). TO = float or __half.
template<int BN, typename TO>
__global__ void __launch_bounds__(256)
k_gemm_h(const __half* __restrict__ A, const uint32_t* __restrict__ Wp,
         const float* __restrict__ bias, const float* __restrict__ res,
         TO* __restrict__ C, int M, int N, int K) {
    constexpr int BM = 128;
    constexpr int AST2 = 20;                 // u32 per A row (40 halves): bank-clean
    constexpr int BST2 = BN + 8;
    constexpr int WN = 32;
    constexpr int WM = (BN == 128) ? 64 : 32;
    constexpr int WARPS_N = BN / WN;
    constexpr int MT = WM / 16;
    constexpr int NT = WN / 8;
    __shared__ uint32_t As[2][BM * AST2];
    __shared__ uint32_t Bs[2][16 * BST2];

    int tid  = threadIdx.x;
    int warp = tid >> 5, lane = tid & 31;
    int gid  = lane >> 2, tg = lane & 3;
    int wm   = warp / WARPS_N, wn = warp % WARPS_N;
    int row0 = blockIdx.y * BM, col0 = blockIdx.x * BN;

    float acc[MT][NT][4];
    #pragma unroll
    for (int i = 0; i < MT; i++)
        #pragma unroll
        for (int j = 0; j < NT; j++)
            #pragma unroll
            for (int q = 0; q < 4; q++) acc[i][j][q] = 0.f;

    const int ntiles = K / 32;

    auto load_tile = [&](int t, int buf) {
        int kt = t * 32;
        int kt2 = t * 16;
        #pragma unroll
        for (int i = 0; i < 2; i++) {
            int ch = tid + i * 256;
            int m = ch >> 2, kc = ch & 3;
            cp_async16(smem_u32(&As[buf][m * AST2 + kc * 4]),
                       A + (size_t)(row0 + m) * K + kt + kc * 8);
        }
        #pragma unroll
        for (int i = 0; i < BN / 64; i++) {
            int ch = tid + i * 256;
            int k2 = ch / (BN / 4), nc = ch % (BN / 4);
            cp_async16(smem_u32(&Bs[buf][k2 * BST2 + nc * 4]),
                       Wp + (size_t)(kt2 + k2) * N + col0 + nc * 4);
        }
    };

    load_tile(0, 0);
    cp_commit();

    for (int t = 0; t < ntiles; t++) {
        int buf = t & 1;
        if (t + 1 < ntiles) {
            load_tile(t + 1, buf ^ 1);
            cp_commit();
            cp_wait<1>();
        } else {
            cp_wait<0>();
        }
        __syncthreads();

        #pragma unroll
        for (int ks = 0; ks < 2; ks++) {
            uint32_t af[MT][4], bf[NT][2];
            #pragma unroll
            for (int mt = 0; mt < MT; mt++) {
                int m0 = wm * WM + mt * 16;
                af[mt][0] = As[buf][(m0 + gid    ) * AST2 + ks * 8 + tg    ];
                af[mt][1] = As[buf][(m0 + gid + 8) * AST2 + ks * 8 + tg    ];
                af[mt][2] = As[buf][(m0 + gid    ) * AST2 + ks * 8 + tg + 4];
                af[mt][3] = As[buf][(m0 + gid + 8) * AST2 + ks * 8 + tg + 4];
            }
            #pragma unroll
            for (int nt = 0; nt < NT; nt++) {
                int n0 = wn * WN + nt * 8 + gid;
                bf[nt][0] = Bs[buf][(ks * 8 + tg    ) * BST2 + n0];
                bf[nt][1] = Bs[buf][(ks * 8 + tg + 4) * BST2 + n0];
            }
            #pragma unroll
            for (int mt = 0; mt < MT; mt++)
                #pragma unroll
                for (int nt = 0; nt < NT; nt++)
                    mma_f16(acc[mt][nt], af[mt], bf[nt]);
        }
        __syncthreads();
    }

    #pragma unroll
    for (int mt = 0; mt < MT; mt++) {
        #pragma unroll
        for (int nt = 0; nt < NT; nt++) {
            int r0 = row0 + wm * WM + mt * 16 + gid;
            int c  = col0 + wn * WN + nt * 8 + tg * 2;
            float v0 = acc[mt][nt][0], v1 = acc[mt][nt][1];
            float v2 = acc[mt][nt][2], v3 = acc[mt][nt][3];
            if (bias) {
                float b0 = bias[c], b1 = bias[c + 1];
                v0 += b0; v1 += b1; v2 += b0; v3 += b1;
            }
            if (res) {
                v0 += res[(size_t)r0 * N + c];
                v1 += res[(size_t)r0 * N + c + 1];
                v2 += res[(size_t)(r0 + 8) * N + c];
                v3 += res[(size_t)(r0 + 8) * N + c + 1];
            }
            if constexpr (sizeof(TO) == 2) {
                *(uint32_t*)&C[(size_t)r0 * N + c]       = packh2(v0, v1);
                *(uint32_t*)&C[(size_t)(r0 + 8) * N + c] = packh2(v2, v3);
            } else {
                C[(size_t)r0 * N + c]           = v0;
                C[(size_t)r0 * N + c + 1]       = v1;
                C[(size_t)(r0 + 8) * N + c]     = v2;
                C[(size_t)(r0 + 8) * N + c + 1] = v3;
            }
        }
    }
}

// ---------------- col attention (fp16 qkv input) ----------------
__global__ void k_colattn(const __half* __restrict__ qkv, __half* __restrict__ out) {
    int s = blockIdx.x, h = blockIdx.y;
    __shared__ float q[32][64], k[32][65], v[32][64], p[32][32];
    int tid = threadIdx.x;
    #pragma unroll
    for (int i = 0; i < 8; i++) {
        int idx = tid + i * 256;
        int r = idx >> 6, d = idx & 63;
        int base = (s * 32 + r) * 1536 + h * 64 + d;
        q[r][d] = __half2float(qkv[base]);
        k[r][d] = __half2float(qkv[base + 512]);
        v[r][d] = __half2float(qkv[base + 1024]);
    }
    __syncthreads();
    #pragma unroll
    for (int i = 0; i < 4; i++) {
        int idx = tid + i * 256;
        int r = idx >> 5, c = idx & 31;
        float acc = 0.f;
        #pragma unroll
        for (int d = 0; d < 64; d++) acc += q[r][d] * k[c][d];
        p[r][c] = acc * 0.125f;
    }
    __syncthreads();
    int lane = tid & 31, w = tid >> 5;
    #pragma unroll
    for (int rr = 0; rr < 4; rr++) {
        int r = w * 4 + rr;
        float x = p[r][lane];
        float mx = x;
        #pragma unroll
        for (int o = 16; o; o >>= 1) mx = fmaxf(mx, __shfl_xor_sync(0xffffffffu, mx, o));
        float e = expf(x - mx);
        float sm2 = e;
        #pragma unroll
        for (int o = 16; o; o >>= 1) sm2 += __shfl_xor_sync(0xffffffffu, sm2, o);
        p[r][lane] = tf32(e / sm2);
    }
    __syncthreads();
    #pragma unroll
    for (int i = 0; i < 8; i++) {
        int idx = tid + i * 256;
        int r = idx >> 6, d = idx & 63;
        float acc = 0.f;
        #pragma unroll
        for (int j = 0; j < 32; j++) acc += p[r][j] * v[j][d];
        out[(s * 32 + r) * 512 + h * 64 + d] = __float2half_rn(acc);
    }
}

// ---------------- row attention: fp16 mma flash ----------------
// CTA: 64 queries x 1 head, 128 threads = 4 warps; warp w owns queries [w*16, w*16+16).
// Per 64-key tile: QK (32 mmas/warp), fragment online softmax, PV (32 mmas/warp).
__global__ void __launch_bounds__(128)
k_rowattn(const __half* __restrict__ qkv, __half* __restrict__ out) {
    constexpr int KST = 72;   // halves per Ks/Vs row
    __shared__ __half Ks[64 * KST];
    __shared__ __half Vs[64 * KST];
    int tid = threadIdx.x, warp = tid >> 5, lane = tid & 31;
    int gid = lane >> 2, tg = lane & 3;
    int h = blockIdx.y;
    int q0 = blockIdx.x * 64 + warp * 16;    // first query row of this warp

    // preload Q fragments: A[16 x 64] -> 4 ksteps x 4 u32
    uint32_t qf[4][4];
    #pragma unroll
    for (int ks = 0; ks < 4; ks++) {
        const __half* qb = qkv + (size_t)q0 * 1536 + h * 64 + ks * 16 + 2 * tg;
        qf[ks][0] = *(const uint32_t*)(qb + (size_t)gid * 1536);
        qf[ks][1] = *(const uint32_t*)(qb + (size_t)(gid + 8) * 1536);
        qf[ks][2] = *(const uint32_t*)(qb + (size_t)gid * 1536 + 8);
        qf[ks][3] = *(const uint32_t*)(qb + (size_t)(gid + 8) * 1536 + 8);
    }

    float m0 = -1e30f, m1 = -1e30f, l0 = 0.f, l1 = 0.f;
    float of[8][4];
    #pragma unroll
    for (int nf = 0; nf < 8; nf++)
        #pragma unroll
        for (int q = 0; q < 4; q++) of[nf][q] = 0.f;

    for (int kt = 0; kt < KTILES; kt++) {
        // fill K/V tiles (64 keys x 64 d halves), half2 loads
        #pragma unroll
        for (int i = 0; i < 16; i++) {
            int idx = tid + i * 128;
            int r = idx >> 5, d2 = idx & 31;
            const __half* kb = qkv + (size_t)(kt * 64 + r) * 1536 + 512 + h * 64 + d2 * 2;
            *(uint32_t*)&Ks[r * KST + d2 * 2] = *(const uint32_t*)kb;
            *(uint32_t*)&Vs[r * KST + d2 * 2] = *(const uint32_t*)(kb + 512);
        }
        __syncthreads();

        // QK: S[16 x 64]
        float sf[8][4];
        #pragma unroll
        for (int nf = 0; nf < 8; nf++)
            #pragma unroll
            for (int q = 0; q < 4; q++) sf[nf][q] = 0.f;
        #pragma unroll
        for (int ks = 0; ks < 4; ks++) {
            #pragma unroll
            for (int nf = 0; nf < 8; nf++) {
                uint32_t b[2];
                b[0] = *(const uint32_t*)&Ks[(nf * 8 + gid) * KST + ks * 16 + 2 * tg];
                b[1] = *(const uint32_t*)&Ks[(nf * 8 + gid) * KST + ks * 16 + 2 * tg + 8];
                mma_f16(sf[nf], qf[ks], b);
            }
        }

        // online softmax on fragments (rows gid -> m0/l0, gid+8 -> m1/l1)
        float mx0 = m0, mx1 = m1;
        #pragma unroll
        for (int nf = 0; nf < 8; nf++) {
            sf[nf][0] *= 0.125f; sf[nf][1] *= 0.125f;
            sf[nf][2] *= 0.125f; sf[nf][3] *= 0.125f;
            mx0 = fmaxf(mx0, fmaxf(sf[nf][0], sf[nf][1]));
            mx1 = fmaxf(mx1, fmaxf(sf[nf][2], sf[nf][3]));
        }
        mx0 = fmaxf(mx0, __shfl_xor_sync(0xffffffffu, mx0, 1));
        mx0 = fmaxf(mx0, __shfl_xor_sync(0xffffffffu, mx0, 2));
        mx1 = fmaxf(mx1, __shfl_xor_sync(0xffffffffu, mx1, 1));
        mx1 = fmaxf(mx1, __shfl_xor_sync(0xffffffffu, mx1, 2));
        float f0 = expf(m0 - mx0), f1 = expf(m1 - mx1);
        m0 = mx0; m1 = mx1;
        float ps0 = 0.f, ps1 = 0.f;
        #pragma unroll
        for (int nf = 0; nf < 8; nf++) {
            sf[nf][0] = expf(sf[nf][0] - m0); ps0 += sf[nf][0];
            sf[nf][1] = expf(sf[nf][1] - m0); ps0 += sf[nf][1];
            sf[nf][2] = expf(sf[nf][2] - m1); ps1 += sf[nf][2];
            sf[nf][3] = expf(sf[nf][3] - m1); ps1 += sf[nf][3];
        }
        ps0 += __shfl_xor_sync(0xffffffffu, ps0, 1);
        ps0 += __shfl_xor_sync(0xffffffffu, ps0, 2);
        ps1 += __shfl_xor_sync(0xffffffffu, ps1, 1);
        ps1 += __shfl_xor_sync(0xffffffffu, ps1, 2);
        l0 = l0 * f0 + ps0;
        l1 = l1 * f1 + ps1;
        #pragma unroll
        for (int nf = 0; nf < 8; nf++) {
            of[nf][0] *= f0; of[nf][1] *= f0;
            of[nf][2] *= f1; of[nf][3] *= f1;
        }

        // PV: O[16 x 64] += P[16 x 64keys] @ V[64keys x 64d]
        #pragma unroll
        for (int ks = 0; ks < 4; ks++) {
            uint32_t pa[4];
            pa[0] = packh2(sf[2 * ks][0], sf[2 * ks][1]);
            pa[1] = packh2(sf[2 * ks][2], sf[2 * ks][3]);
            pa[2] = packh2(sf[2 * ks + 1][0], sf[2 * ks + 1][1]);
            pa[3] = packh2(sf[2 * ks + 1][2], sf[2 * ks + 1][3]);
            int k0 = ks * 16 + 2 * tg;
            #pragma unroll
            for (int nf = 0; nf < 8; nf++) {
                int n = nf * 8 + gid;
                uint32_t b[2];
                b[0] = ((uint32_t)__half_as_ushort(Vs[(k0 + 1) * KST + n]) << 16)
                     | __half_as_ushort(Vs[k0 * KST + n]);
                b[1] = ((uint32_t)__half_as_ushort(Vs[(k0 + 9) * KST + n]) << 16)
                     | __half_as_ushort(Vs[(k0 + 8) * KST + n]);
                mma_f16(of[nf], pa, b);
            }
        }
        __syncthreads();
    }

    float inv0 = 1.f / l0, inv1 = 1.f / l1;
    #pragma unroll
    for (int nf = 0; nf < 8; nf++) {
        int c = h * 64 + nf * 8 + 2 * tg;
        *(uint32_t*)&out[(size_t)(q0 + gid) * 512 + c] =
            packh2(of[nf][0] * inv0, of[nf][1] * inv0);
        *(uint32_t*)&out[(size_t)(q0 + gid + 8) * 512 + c] =
            packh2(of[nf][2] * inv1, of[nf][3] * inv1);
    }
}

// ---------------- GEGLU ----------------
__global__ void k_geglu(const float* __restrict__ h, __half* __restrict__ out, int M, int F) {
    int i = blockIdx.x * 256 + threadIdx.x;
    if (i >= M * F) return;
    int r = i / F, c = i - r * F;
    float a = h[r * 2 * F + c];
    float g = h[r * 2 * F + F + c];
    out[i] = __float2half_rn(a * 0.5f * g * (1.f + erff(g * 0.70710678118654752f)));
}

__global__ void k_copy(const float* __restrict__ in, float* __restrict__ out, int n) {
    int i = blockIdx.x * 256 + threadIdx.x;
    if (i < n) out[i] = in[i];
}

// ---------------- driver ----------------
extern "C" void kernel_launch(void* const* d_in, const int* in_sizes, int n_in,
                              void* d_out, int out_size) {
    const float* x       = (const float*)d_in[0];
    const float* x_cont  = (const float*)d_in[1];
    const float* c_ln1_g = (const float*)d_in[2];
    const float* c_ln1_b = (const float*)d_in[3];
    const float* c_wqkv  = (const float*)d_in[4];
    const float* c_wo_w  = (const float*)d_in[5];
    const float* c_wo_b  = (const float*)d_in[6];
    const float* c_ln2_g = (const float*)d_in[7];
    const float* c_ln2_b = (const float*)d_in[8];
    const float* c_w1    = (const float*)d_in[9];
    const float* c_b1    = (const float*)d_in[10];
    const float* c_w2    = (const float*)d_in[11];
    const float* c_b2    = (const float*)d_in[12];
    const float* r_ln1_g = (const float*)d_in[13];
    const float* r_ln1_b = (const float*)d_in[14];
    const float* r_wqkv  = (const float*)d_in[15];
    const float* r_wo_w  = (const float*)d_in[16];
    const float* r_wo_b  = (const float*)d_in[17];
    const float* r_ln2_g = (const float*)d_in[18];
    const float* r_ln2_b = (const float*)d_in[19];
    const float* r_w1    = (const float*)d_in[20];
    const float* r_b1    = (const float*)d_in[21];
    const float* r_w2    = (const float*)d_in[22];
    const float* r_b2    = (const float*)d_in[23];

    float *px, *pxn, *ph;
    __half *pxnrh, *pqkvh, *path, *pgh;
    uint32_t *pwrh;
    cudaGetSymbolAddress((void**)&px,    g_x);
    cudaGetSymbolAddress((void**)&pxn,   g_xn);
    cudaGetSymbolAddress((void**)&pxnrh, g_xnrh);
    cudaGetSymbolAddress((void**)&pqkvh, g_qkvh);
    cudaGetSymbolAddress((void**)&path,  g_ath);
    cudaGetSymbolAddress((void**)&ph,    g_h);
    cudaGetSymbolAddress((void**)&pgh,   g_gh);
    cudaGetSymbolAddress((void**)&pwrh,  g_wrh);

    // pack all weights to k-paired fp16 (n_out = floats/2)
    k_packh<<<(196608) / 256, 256>>>(c_wqkv, pwrh + OFF2_CQKV, 196608, 1536);
    k_packh<<<(65536) / 256, 256>>>(c_wo_w, pwrh + OFF2_CWO, 65536, 64);
    k_packh<<<(65536) / 256, 256>>>(c_w1, pwrh + OFF2_CW1, 65536, 512);
    k_packh<<<(32768) / 256, 256>>>(c_w2, pwrh + OFF2_CW2, 32768, 64);
    k_packh<<<(6291456) / 256, 256>>>(r_wqkv, pwrh + OFF2_RQKV, 6291456, 1536);
    k_packh<<<(2097152) / 256, 256>>>(r_wo_w, pwrh + OFF2_RWO, 2097152, 2048);
    k_packh<<<(8388608) / 256, 256>>>(r_w1, pwrh + OFF2_RW1, 8388608, 2048);
    k_packh<<<(4194304) / 256, 256>>>(r_w2, pwrh + OFF2_RW2, 4194304, 2048);

    k_concat<<<(TOK * 64) / 256, 256>>>(x, x_cont, px);

    for (int L = 0; L < DEPTH; L++) {
        // ----- col block -----
        k_ln64<<<TOK / 8, 256>>>(px, c_ln1_g + L * 64, c_ln1_b + L * 64, pxn, pxnrh);
        k_gemm_h<128, __half><<<dim3(12, 512), 256>>>(
            pxnrh, pwrh + OFF2_CQKV + L * 49152, nullptr, nullptr, pqkvh, TOK, 1536, 64);
        k_colattn<<<dim3(BSAMP, HEADS), 256>>>(pqkvh, path);
        k_gemm_h<64, float><<<dim3(1, 512), 256>>>(
            path, pwrh + OFF2_CWO + L * 16384, c_wo_b + L * 64, pxn, px, TOK, 64, 512);
        k_ln64<<<TOK / 8, 256>>>(px, c_ln2_g + L * 64, c_ln2_b + L * 64, pxn, pxnrh);
        k_gemm_h<128, float><<<dim3(4, 512), 256>>>(
            pxnrh, pwrh + OFF2_CW1 + L * 16384, c_b1 + L * 512, nullptr, ph, TOK, 512, 64);
        k_geglu<<<(TOK * DICOL) / 256, 256>>>(ph, pgh, TOK, DICOL);
        k_gemm_h<64, float><<<dim3(1, 512), 256>>>(
            pgh, pwrh + OFF2_CW2 + L * 8192, c_b2 + L * 64, pxn, px, TOK, 64, 256);

        // ----- row block (x viewed as [2048, 2048]) -----
        k_ln2048<<<BSAMP, 256>>>(px, r_ln1_g + L * 2048, r_ln1_b + L * 2048, pxn, pxnrh);
        k_gemm_h<128, __half><<<dim3(12, 16), 256>>>(
            pxnrh, pwrh + OFF2_RQKV + (size_t)L * 1572864, nullptr, nullptr, pqkvh, BSAMP, 1536, 2048);
        k_rowattn<<<dim3(BSAMP / 64, HEADS), 128>>>(pqkvh, path);
        k_gemm_h<128, float><<<dim3(16, 16), 256>>>(
            path, pwrh + OFF2_RWO + (size_t)L * 524288, r_wo_b + L * 2048, pxn, px, BSAMP, 2048, 512);
        k_ln2048<<<BSAMP, 256>>>(px, r_ln2_g + L * 2048, r_ln2_b + L * 2048, pxn, pxnrh);
        k_gemm_h<128, float><<<dim3(16, 16), 256>>>(
            pxnrh, pwrh + OFF2_RW1 + (size_t)L * 2097152, r_b1 + L * 2048, nullptr, ph, BSAMP, 2048, 2048);
        k_geglu<<<(BSAMP * DIROW) / 256, 256>>>(ph, pgh, BSAMP, DIROW);
        k_gemm_h<128, float><<<dim3(16, 16), 256>>>(
            pgh, pwrh + OFF2_RW2 + (size_t)L * 1048576, r_b2 + L * 2048, pxn, px, BSAMP, 2048, 1024);
    }

    k_copy<<<(TOK * 64) / 256, 256>>>(px, (float*)d_out, TOK * 64);
}